// round 14
// baseline (speedup 1.0000x reference)
#include <cuda_runtime.h>
#include <cuda_bf16.h>
#include <math_constants.h>

#define T_SRC   4096
#define T_DST   4096
#define HID     128
#define NHEADS  8
#define KTOP    128
#define TDENSE  1024
#define NT      512
#define QT      8
#define NW      (NT / 32)
#define NTILES  (T_DST / QT)
#define NBLK_MAX (T_SRC / 16)   // 256 key-blocks of 16
#define KSTEP    (HID / 16)     // 8 k-steps of 16 dims (bf16 mma)
#define NJBLK    (T_SRC / 8)    // V frags
#define NDTILE   (HID / 16)

#define HPAD      264
#define CAND_CAP  1536
#define C2_CAP    256

#define W_SC    (QT * T_SRC)
#define W_Q     (QT * HID)
#define W_IDX   (QT * KTOP)
#define W_W     (QT * KTOP)
#define W_H3    (QT * HPAD)
#define W_CAND  (QT * CAND_CAP)
#define W_C2    (QT * C2_CAP)
#define W_EQ    KTOP
#define W_CTRL  64
#define W_SEL   (W_H3 + W_CAND + W_C2 + W_EQ + W_CTRL)
#define DYN_BYTES ((W_SC + W_Q + W_IDX + W_W + W_SEL) * 4)

// K as packed bf16 hi/lo mma A-fragments: [h][blk][st][lane][{hi,lo}] uint4
#define KFRAGB_N (NHEADS * NBLK_MAX * KSTEP * 32 * 2)
__device__ uint4 g_kfragb[KFRAGB_N];
// V^T tf32-path fragments (dense AV), raw floats
#define VFRAG_N (NHEADS * NDTILE * NJBLK * 32)
__device__ float4 g_vfrag[VFRAG_N];

__device__ __forceinline__ unsigned fkey(float f) {
    unsigned b = __float_as_uint(f);
    return b ^ ((b & 0x80000000u) ? 0xFFFFFFFFu : 0x80000000u);
}

__device__ __forceinline__ unsigned tf32_hi_bits(float x) {
    return __float_as_uint(x) & 0xFFFFE000u;
}

__device__ __forceinline__ unsigned pack_bf16(float a, float b) {
    __nv_bfloat162 p = __floats2bfloat162_rn(a, b);
    return *(unsigned*)&p;
}
__device__ __forceinline__ float bf16_lo_res(float x) {
    __nv_bfloat16 hb = __float2bfloat16_rn(x);
    return x - __bfloat162float(hb);
}
__device__ __forceinline__ float bf16_val(float x) {
    return __bfloat162float(__float2bfloat16_rn(x));
}

__device__ __forceinline__ void mma_bf16(float& d0, float& d1, float& d2, float& d3,
                                         unsigned a0, unsigned a1, unsigned a2, unsigned a3,
                                         unsigned b0, unsigned b1) {
    asm volatile(
        "mma.sync.aligned.m16n8k16.row.col.f32.bf16.bf16.f32 "
        "{%0,%1,%2,%3}, {%4,%5,%6,%7}, {%8,%9}, {%0,%1,%2,%3};"
        : "+f"(d0), "+f"(d1), "+f"(d2), "+f"(d3)
        : "r"(a0), "r"(a1), "r"(a2), "r"(a3), "r"(b0), "r"(b1));
}

__device__ __forceinline__ void mma_tf32(float& d0, float& d1, float& d2, float& d3,
                                         unsigned a0, unsigned a1, unsigned a2, unsigned a3,
                                         unsigned b0, unsigned b1) {
    asm volatile(
        "mma.sync.aligned.m16n8k8.row.col.f32.tf32.tf32.f32 "
        "{%0,%1,%2,%3}, {%4,%5,%6,%7}, {%8,%9}, {%0,%1,%2,%3};"
        : "+f"(d0), "+f"(d1), "+f"(d2), "+f"(d3)
        : "r"(a0), "r"(a1), "r"(a2), "r"(a3), "r"(b0), "r"(b1));
}

__device__ __forceinline__ float block_max(float v, float* sred) {
    #pragma unroll
    for (int o = 16; o; o >>= 1) v = fmaxf(v, __shfl_xor_sync(0xFFFFFFFFu, v, o));
    if ((threadIdx.x & 31) == 0) sred[threadIdx.x >> 5] = v;
    __syncthreads();
    if (threadIdx.x < 32) {
        float x = (threadIdx.x < NW) ? sred[threadIdx.x] : -CUDART_INF_F;
        #pragma unroll
        for (int o = 8; o; o >>= 1) x = fmaxf(x, __shfl_xor_sync(0xFFFFFFFFu, x, o));
        if (threadIdx.x == 0) sred[0] = x;
    }
    __syncthreads();
    v = sred[0];
    __syncthreads();
    return v;
}

__device__ __forceinline__ float block_sum(float v, float* sred) {
    #pragma unroll
    for (int o = 16; o; o >>= 1) v += __shfl_xor_sync(0xFFFFFFFFu, v, o);
    if ((threadIdx.x & 31) == 0) sred[threadIdx.x >> 5] = v;
    __syncthreads();
    if (threadIdx.x < 32) {
        float x = (threadIdx.x < NW) ? sred[threadIdx.x] : 0.0f;
        #pragma unroll
        for (int o = 8; o; o >>= 1) x += __shfl_xor_sync(0xFFFFFFFFu, x, o);
        if (threadIdx.x == 0) sred[0] = x;
    }
    __syncthreads();
    v = sred[0];
    __syncthreads();
    return v;
}

// ---- precompute: K -> packed bf16 hi/lo fragments (m16n8k16 A layout) ----
__global__ void swizzle_kb_kernel(const float* __restrict__ k) {
    int t = blockIdx.x * blockDim.x + threadIdx.x;   // NHEADS*NBLK*KSTEP*32 threads
    int lane = t & 31;
    int st   = (t >> 5) & (KSTEP - 1);
    int blk  = (t >> 8) & (NBLK_MAX - 1);
    int h    = t >> 16;
    int g  = lane >> 2;
    int t4 = lane & 3;
    int key = blk * 16 + g;
    int c0 = st * 16 + 2 * t4;       // cols for a0/a1
    int c2 = c0 + 8;                 // cols for a2/a3
    const float* r0 = k + ((size_t)(h * T_SRC + key)) * HID;
    const float* r1 = r0 + 8 * HID;
    float x0 = r0[c0], x1 = r0[c0 + 1];
    float x2 = r1[c0], x3 = r1[c0 + 1];
    float x4 = r0[c2], x5 = r0[c2 + 1];
    float x6 = r1[c2], x7 = r1[c2 + 1];
    uint4 hi, lo;
    hi.x = pack_bf16(x0, x1); lo.x = pack_bf16(x0 - bf16_val(x0), x1 - bf16_val(x1));
    hi.y = pack_bf16(x2, x3); lo.y = pack_bf16(x2 - bf16_val(x2), x3 - bf16_val(x3));
    hi.z = pack_bf16(x4, x5); lo.z = pack_bf16(x4 - bf16_val(x4), x5 - bf16_val(x5));
    hi.w = pack_bf16(x6, x7); lo.w = pack_bf16(x6 - bf16_val(x6), x7 - bf16_val(x7));
    size_t idx = ((((size_t)h * NBLK_MAX + blk) * KSTEP + st) * 32 + lane) * 2;
    g_kfragb[idx]     = hi;
    g_kfragb[idx + 1] = lo;
}

// ---- precompute: V^T in tf32 mma A-fragment order ----
__global__ void swizzle_v_kernel(const float* __restrict__ v) {
    int t = blockIdx.x * blockDim.x + threadIdx.x;
    int lane = t & 31;
    int jb   = (t >> 5) & (NJBLK - 1);
    int dt   = (t >> 14) & (NDTILE - 1);
    int h    = t >> 17;
    int g  = lane >> 2;
    int tg = lane & 3;
    int d  = dt * 16 + g;
    int j  = jb * 8 + tg;
    const float* vb = v + (size_t)(h * T_SRC) * HID;
    g_vfrag[t] = make_float4(vb[(size_t)j * HID + d],
                             vb[(size_t)j * HID + d + 8],
                             vb[(size_t)(j + 4) * HID + d],
                             vb[(size_t)(j + 4) * HID + d + 8]);
}

__global__ __launch_bounds__(NT, 1)
void tree_attn_r14(const float* __restrict__ q,
                   const float* __restrict__ v,
                   float* __restrict__ out) {
    extern __shared__ char smem_raw[];
    float*    s_sc   = (float*)smem_raw;                     // [QT][T_SRC]
    float*    s_q    = s_sc + W_SC;                          // [QT][HID]
    int*      s_idx  = (int*)(s_q + W_Q);                    // [QT][KTOP]
    float*    s_w    = (float*)(s_idx + W_IDX);              // [QT][KTOP]
    unsigned* s_h3   = (unsigned*)(s_w + W_W);               // [QT][HPAD]
    int*      s_cand = (int*)(s_h3 + W_H3);                  // [QT][CAND_CAP]
    int*      s_c2   = (int*)(s_cand + W_CAND);              // [QT][C2_CAP]
    int*      s_eq   = (int*)(s_c2 + W_C2);                  // [KTOP]
    unsigned* s_ctrl = (unsigned*)(s_eq + W_EQ);             // [W_CTRL]
    float*    s_buf  = (float*)s_h3;                         // [NT] union (sparse AV)
    float*    s_av   = (float*)s_h3;                         // [2][8][128] union (dense AV)
    unsigned* s_b3   = s_ctrl;
    unsigned* s_ngt3 = s_ctrl + 8;
    unsigned* s_gtc  = s_ctrl + 16;
    unsigned* s_cc   = s_ctrl + 24;
    unsigned* s_ovf  = s_ctrl + 32;
    unsigned* s_misc = s_ctrl + 40;
    float*    s_inv  = (float*)(s_ctrl + 48);
    __shared__ float s_redf[NW];

    const int tile = (NTILES - 1) - blockIdx.x;
    const int h    = blockIdx.y;
    const int tid  = threadIdx.x;
    const int wid  = tid >> 5;
    const int lane = tid & 31;
    const unsigned lmlt = (1u << lane) - 1u;
    const int qi0  = tile * QT;
    const int n_max = qi0 + QT;
    const bool sparse = (qi0 >= TDENSE);

    const float* vbase = v + (size_t)h * T_SRC * HID;

    for (int d = tid; d < QT * HID; d += NT)
        s_q[d] = q[((size_t)h * T_DST + qi0) * HID + d];
    if (sparse) {
        for (int i = tid; i < QT * HPAD; i += NT) s_h3[i] = 0u;
        if (tid < 8) { s_gtc[tid] = 0u; s_cc[tid] = 0u; s_ovf[tid] = 0u; }
    }
    __syncthreads();

    // ---- B (query) bf16 hi/lo fragments in registers (m16n8k16 B layout) ----
    const int g  = lane >> 2;   // 0..7
    const int tg = lane & 3;
    unsigned qb0h[KSTEP], qb1h[KSTEP], qb0l[KSTEP], qb1l[KSTEP];
    #pragma unroll
    for (int st = 0; st < KSTEP; st++) {
        int c = st * 16 + 2 * tg;
        float y0 = s_q[g * HID + c],     y1 = s_q[g * HID + c + 1];
        float y2 = s_q[g * HID + c + 8], y3 = s_q[g * HID + c + 9];
        qb0h[st] = pack_bf16(y0, y1);
        qb1h[st] = pack_bf16(y2, y3);
        qb0l[st] = pack_bf16(y0 - bf16_val(y0), y1 - bf16_val(y1));
        qb1l[st] = pack_bf16(y2 - bf16_val(y2), y3 - bf16_val(y3));
    }

    // ---- scores via 3x bf16 mma, fused histogram ----
    float mx[QT];
    #pragma unroll
    for (int s = 0; s < QT; s++) mx[s] = -CUDART_INF_F;

    const int nblk = (n_max + 15) >> 4;
    for (int blk = wid; blk < nblk; blk += NW) {
        float d0 = 0.f, d1 = 0.f, d2 = 0.f, d3 = 0.f;
        const uint4* fk = g_kfragb + (((size_t)(h * NBLK_MAX + blk) * KSTEP) * 32 + lane) * 2;
        #pragma unroll
        for (int st = 0; st < KSTEP; st++) {
            uint4 ahi = fk[st * 64];
            uint4 alo = fk[st * 64 + 1];
            mma_bf16(d0, d1, d2, d3, ahi.x, ahi.y, ahi.z, ahi.w, qb0h[st], qb1h[st]);  // hi*hi
            mma_bf16(d0, d1, d2, d3, ahi.x, ahi.y, ahi.z, ahi.w, qb0l[st], qb1l[st]);  // hi*lo
            mma_bf16(d0, d1, d2, d3, alo.x, alo.y, alo.z, alo.w, qb0h[st], qb1h[st]);  // lo*hi
        }
        const int kA = blk * 16 + g;
        const int kB = kA + 8;
        const int q0 = tg * 2;
        const int q1 = q0 + 1;
        float v0 = (kA <= qi0 + q0) ? d0 : -CUDART_INF_F;
        float v1 = (kA <= qi0 + q1) ? d1 : -CUDART_INF_F;
        float v2 = (kB <= qi0 + q0) ? d2 : -CUDART_INF_F;
        float v3 = (kB <= qi0 + q1) ? d3 : -CUDART_INF_F;
        s_sc[q0 * T_SRC + kA] = v0;
        s_sc[q1 * T_SRC + kA] = v1;
        s_sc[q0 * T_SRC + kB] = v2;
        s_sc[q1 * T_SRC + kB] = v3;
        mx[q0] = fmaxf(mx[q0], fmaxf(v0, v2));
        mx[q1] = fmaxf(mx[q1], fmaxf(v1, v3));
        if (sparse) {
            atomicAdd(&s_h3[q0 * HPAD + (fkey(v0) >> 24)], 1u);
            atomicAdd(&s_h3[q1 * HPAD + (fkey(v1) >> 24)], 1u);
            atomicAdd(&s_h3[q0 * HPAD + (fkey(v2) >> 24)], 1u);
            atomicAdd(&s_h3[q1 * HPAD + (fkey(v3) >> 24)], 1u);
        }
    }
    __syncthreads();

    float m[QT];
    #pragma unroll
    for (int s = 0; s < QT; s++) m[s] = block_max(mx[s], s_redf);

    if (!sparse) {
        // ================= dense causal softmax =================
        float psum[QT];
        #pragma unroll
        for (int s = 0; s < QT; s++) psum[s] = 0.0f;
        for (int j = tid; j < n_max; j += NT) {
            #pragma unroll
            for (int s = 0; s < QT; s++) {
                float sc = s_sc[s * T_SRC + j];
                float e = (j <= qi0 + s) ? __expf(sc - m[s]) : 0.0f;
                s_sc[s * T_SRC + j] = e;
                psum[s] += e;
            }
        }
        #pragma unroll
        for (int s = 0; s < QT; s++) {
            float iv = 1.0f / block_sum(psum[s], s_redf);
            if (tid == 0) s_inv[s] = iv;
        }

        // ---- dense AV via 3xTF32 mma on precomputed V^T fragments ----
        {
            const int dt = wid & 7;
            const int jh = wid >> 3;
            const int jchunks = n_max >> 3;
            float e0 = 0.f, e1 = 0.f, e2 = 0.f, e3 = 0.f;
            const float4* fv = g_vfrag + ((size_t)((h * NDTILE + dt) * NJBLK)) * 32 + lane;
            for (int c = jh; c < jchunks; c += 2) {
                float4 a4 = fv[c * 32];
                unsigned a0 = tf32_hi_bits(a4.x), a1 = tf32_hi_bits(a4.y);
                unsigned a2 = tf32_hi_bits(a4.z), a3 = tf32_hi_bits(a4.w);
                unsigned l0 = __float_as_uint(a4.x - __uint_as_float(a0));
                unsigned l1 = __float_as_uint(a4.y - __uint_as_float(a1));
                unsigned l2 = __float_as_uint(a4.z - __uint_as_float(a2));
                unsigned l3 = __float_as_uint(a4.w - __uint_as_float(a3));
                float p0 = s_sc[g * T_SRC + c * 8 + tg];
                float p1 = s_sc[g * T_SRC + c * 8 + tg + 4];
                unsigned ph0 = tf32_hi_bits(p0);
                unsigned ph1 = tf32_hi_bits(p1);
                unsigned pl0 = __float_as_uint(p0 - __uint_as_float(ph0));
                unsigned pl1 = __float_as_uint(p1 - __uint_as_float(ph1));
                mma_tf32(e0, e1, e2, e3, a0, a1, a2, a3, ph0, ph1);
                mma_tf32(e0, e1, e2, e3, l0, l1, l2, l3, ph0, ph1);
                mma_tf32(e0, e1, e2, e3, a0, a1, a2, a3, pl0, pl1);
            }
            int base = jh * 1024 + (tg * 2) * HID + dt * 16 + g;
            s_av[base]           = e0;
            s_av[base + HID]     = e1;
            s_av[base + 8]       = e2;
            s_av[base + HID + 8] = e3;
        }
        __syncthreads();
        #pragma unroll
        for (int i = tid; i < QT * HID; i += NT) {
            int qq = i >> 7;
            out[((size_t)h * T_DST + qi0 + qq) * HID + (i & (HID - 1))] =
                (s_av[i] + s_av[1024 + i]) * s_inv[qq];
        }
    } else {
        // ================= sparse: exact top-128 =================
        const int bound = ((n_max + NT - 1) / NT) * NT;

        // ---- per-warp bin scan (warps 0..7); histogram already built ----
        if (wid < QT) {
            const int s = wid;
            unsigned gg = 0;
            #pragma unroll
            for (int b = 0; b < 8; b++) gg += s_h3[s * HPAD + lane * 8 + b];
            unsigned run = gg;
            #pragma unroll
            for (int o = 1; o < 32; o <<= 1) {
                unsigned u = __shfl_down_sync(0xFFFFFFFFu, run, o);
                if (lane + o < 32) run += u;
            }
            unsigned S = run - gg;
            int found = (run >= KTOP && S < KTOP);
            unsigned blb = 0, acc2 = 0;
            if (found) {
                acc2 = S;
                #pragma unroll 1
                for (int b = 7; b >= 0; b--) {
                    unsigned c = s_h3[s * HPAD + lane * 8 + b];
                    if (acc2 + c >= KTOP) { blb = lane * 8 + b; break; }
                    acc2 += c;
                }
            }
            unsigned fmask = __ballot_sync(0xFFFFFFFFu, found);
            int flane = __ffs(fmask) - 1;
            blb  = __shfl_sync(0xFFFFFFFFu, blb, flane);
            acc2 = __shfl_sync(0xFFFFFFFFu, acc2, flane);
            if (lane == 0) { s_b3[s] = blb; s_ngt3[s] = acc2; }
        }
        __syncthreads();

        // ---- combined compact sweep ----
        for (int j = tid; j < bound; j += NT) {
            #pragma unroll
            for (int s = 0; s < QT; s++) {
                unsigned bin = 257u;
                if (j < n_max) bin = fkey(s_sc[s * T_SRC + j]) >> 24;
                const unsigned b3v = s_b3[s];
                bool gt = (bin > b3v) && (bin <= 255u);
                bool eq = (bin == b3v);
                unsigned mg = __ballot_sync(0xFFFFFFFFu, gt);
                unsigned me = __ballot_sync(0xFFFFFFFFu, eq);
                unsigned baseg = 0, basee = 0;
                if (mg && lane == (unsigned)(__ffs(mg) - 1))
                    baseg = atomicAdd(&s_gtc[s], (unsigned)__popc(mg));
                if (me && lane == (unsigned)(__ffs(me) - 1))
                    basee = atomicAdd(&s_cc[s], (unsigned)__popc(me));
                if (mg) {
                    baseg = __shfl_sync(0xFFFFFFFFu, baseg, __ffs(mg) - 1);
                    if (gt) s_idx[s * KTOP + baseg + __popc(mg & lmlt)] = j;
                }
                if (me) {
                    basee = __shfl_sync(0xFFFFFFFFu, basee, __ffs(me) - 1);
                    if (eq) {
                        unsigned p = basee + __popc(me & lmlt);
                        if (p < CAND_CAP) s_cand[s * CAND_CAP + p] = j;
                    }
                }
            }
        }
        __syncthreads();

        // ---- per-warp refinement (warps 0..7) ----
        if (wid < QT) {
            const int s = wid;
            const float* sc = s_sc + s * T_SRC;
            int nc = (int)s_cc[s];
            unsigned ngt = s_ngt3[s];
            bool ok = (nc <= CAND_CAP);
            int cur = 0;
            int* lists[2] = { s_cand + s * CAND_CAP, s_c2 + s * C2_CAP };
            const int caps[2] = { CAND_CAP, C2_CAP };

            #pragma unroll 1
            for (int lvl = 2; lvl >= 0 && ok; lvl--) {
                const int shift = lvl * 8;
                for (int b = lane; b < 257; b += 32) s_h3[s * HPAD + b] = 0u;
                __syncwarp();
                const int rb = (nc + 31) & ~31;
                for (int i = lane; i < rb; i += 32) {
                    unsigned bin = 256u;
                    if (i < nc) bin = (fkey(sc[lists[cur][i]]) >> shift) & 255u;
                    unsigned peers = __match_any_sync(0xFFFFFFFFu, bin);
                    if ((__ffs(peers) - 1) == lane)
                        s_h3[s * HPAD + bin] += (unsigned)__popc(peers);
                }
                __syncwarp();
                unsigned gg = 0;
                #pragma unroll
                for (int b = 0; b < 8; b++) gg += s_h3[s * HPAD + lane * 8 + b];
                unsigned run = gg;
                #pragma unroll
                for (int o = 1; o < 32; o <<= 1) {
                    unsigned u = __shfl_down_sync(0xFFFFFFFFu, run, o);
                    if (lane + o < 32) run += u;
                }
                unsigned S = run - gg;
                int found = (ngt + run >= KTOP && ngt + S < KTOP);
                unsigned blb = 0;
                if (found) {
                    unsigned acc2 = ngt + S;
                    #pragma unroll 1
                    for (int b = 7; b >= 0; b--) {
                        unsigned c = s_h3[s * HPAD + lane * 8 + b];
                        if (acc2 + c >= KTOP) { blb = lane * 8 + b; break; }
                        acc2 += c;
                    }
                }
                unsigned fmask = __ballot_sync(0xFFFFFFFFu, found);
                int flane = __ffs(fmask) - 1;
                blb = __shfl_sync(0xFFFFFFFFu, blb, flane);
                const int dst = cur ^ 1;
                int* dl = lists[dst];
                const int dcap = caps[dst];
                unsigned wg = ngt, we = 0;
                for (int i = lane; i < rb; i += 32) {
                    unsigned bin = 256u; int j = 0;
                    if (i < nc) { j = lists[cur][i]; bin = (fkey(sc[j]) >> shift) & 255u; }
                    bool gt = (bin > blb) && (bin <= 255u);
                    bool eq = (bin == blb);
                    unsigned mg = __ballot_sync(0xFFFFFFFFu, gt);
                    unsigned me = __ballot_sync(0xFFFFFFFFu, eq);
                    if (gt) s_idx[s * KTOP + wg + __popc(mg & lmlt)] = j;
                    if (eq) {
                        unsigned p = we + __popc(me & lmlt);
                        if ((int)p < dcap) dl[p] = j;
                    }
                    wg += __popc(mg); we += __popc(me);
                }
                ngt = wg;
                nc = (int)we;
                cur = dst;
                if (nc > dcap) ok = false;
                __syncwarp();
            }
            if (ok) {
                const int need = KTOP - (int)ngt;
                const int* tl = lists[cur];
                for (int i = lane; i < nc; i += 32) {
                    int ji = tl[i];
                    int rank = 0;
                    for (int m2 = 0; m2 < nc; m2++) rank += (tl[m2] < ji);
                    if (rank < need) s_idx[s * KTOP + (int)ngt + rank] = ji;
                }
            } else if (lane == 0) {
                s_ovf[s] = 1u;
            }
        }
        __syncthreads();

        // ---- rare fallback: full 4-level radix ----
        unsigned ovf_any = 0;
        #pragma unroll
        for (int s = 0; s < QT; s++) ovf_any |= s_ovf[s];
        if (ovf_any) {
            #pragma unroll 1
            for (int s = 0; s < QT; s++) {
                if (!s_ovf[s]) continue;
                const float* sc = s_sc + s * T_SRC;
                unsigned prefix = 0, ngt = 0;
                #pragma unroll 1
                for (int level = 3; level >= 0; level--) {
                    for (int b = tid; b < 257; b += NT) s_h3[b] = 0u;
                    __syncthreads();
                    const unsigned shift = level * 8;
                    const unsigned pmask = (level == 3) ? 0u : (0xFFFFFFFFu << (shift + 8));
                    for (int j = tid; j < bound; j += NT) {
                        unsigned bin = 256u;
                        if (j < n_max) {
                            unsigned key = fkey(sc[j]);
                            if ((key & pmask) == prefix) bin = (key >> shift) & 0xFFu;
                        }
                        unsigned peers = __match_any_sync(0xFFFFFFFFu, bin);
                        if ((__ffs(peers) - 1) == lane)
                            atomicAdd(&s_h3[bin], (unsigned)__popc(peers));
                    }
                    __syncthreads();
                    if (tid < 32) {
                        unsigned gg = 0;
                        #pragma unroll
                        for (int b = 0; b < 8; b++) gg += s_h3[tid * 8 + b];
                        unsigned run = gg;
                        #pragma unroll
                        for (int o = 1; o < 32; o <<= 1) {
                            unsigned u = __shfl_down_sync(0xFFFFFFFFu, run, o);
                            if (tid + o < 32) run += u;
                        }
                        unsigned S = run - gg;
                        if (ngt + run >= KTOP && ngt + S < KTOP) {
                            unsigned acc2 = ngt + S;
                            #pragma unroll 1
                            for (int b = 7; b >= 0; b--) {
                                unsigned c = s_h3[tid * 8 + b];
                                if (acc2 + c >= KTOP) {
                                    s_misc[0] = prefix | ((unsigned)(tid * 8 + b) << shift);
                                    s_misc[1] = acc2;
                                    break;
                                }
                                acc2 += c;
                            }
                        }
                    }
                    __syncthreads();
                    prefix = s_misc[0];
                    ngt = s_misc[1];
                    __syncthreads();
                }
                const unsigned t_key = prefix;
                if (tid == 0) { s_misc[2] = 0u; s_misc[3] = 0u; }
                __syncthreads();
                for (int j = tid; j < n_max; j += NT) {
                    unsigned key = fkey(sc[j]);
                    if (key > t_key) {
                        unsigned p = atomicAdd(&s_misc[2], 1u);
                        s_idx[s * KTOP + p] = j;
                    } else if (key == t_key) {
                        unsigned p = atomicAdd(&s_misc[3], 1u);
                        if (p < KTOP) s_eq[p] = j;
                    }
                }
                __syncthreads();
                const int neq = (int)s_misc[3];
                const int need = KTOP - (int)ngt;
                if (need < neq && tid == 0) {
                    int c = (neq < KTOP) ? neq : KTOP;
                    for (int a = 0; a < need; a++) {
                        int mb = a;
                        for (int b = a + 1; b < c; b++)
                            if (s_eq[b] < s_eq[mb]) mb = b;
                        int t2 = s_eq[a]; s_eq[a] = s_eq[mb]; s_eq[mb] = t2;
                    }
                }
                __syncthreads();
                for (int a = tid; a < need; a += NT) s_idx[s * KTOP + (int)ngt + a] = s_eq[a];
                __syncthreads();
            }
        }

        // ---- per-warp softmax weights (warps 0..7) ----
        if (wid < QT) {
            const int s = wid;
            float psum = 0.0f;
            #pragma unroll
            for (int i = 0; i < KTOP / 32; i++) {
                int a = lane + i * 32;
                float e = __expf(s_sc[s * T_SRC + s_idx[s * KTOP + a]] - m[s]);
                s_w[s * KTOP + a] = e;
                psum += e;
            }
            #pragma unroll
            for (int o = 16; o; o >>= 1) psum += __shfl_xor_sync(0xFFFFFFFFu, psum, o);
            if (lane == 0) s_inv[s] = 1.0f / psum;
        }
        __syncthreads();

        // ---- AV over gathered rows ----
        const int d  = tid & (HID - 1);
        const int qr = tid >> 7;
        float acc[QT];
        #pragma unroll
        for (int s = 0; s < QT; s++) acc[s] = 0.0f;
        for (int a = qr; a < KTOP; a += 4) {
            #pragma unroll
            for (int s = 0; s < QT; s++) {
                int j = s_idx[s * KTOP + a];
                acc[s] = fmaf(s_w[s * KTOP + a], vbase[(size_t)j * HID + d], acc[s]);
            }
        }
        #pragma unroll
        for (int s = 0; s < QT; s++) {
            __syncthreads();
            s_buf[tid] = acc[s];
            __syncthreads();
            if (tid < HID)
                out[((size_t)h * T_DST + qi0 + s) * HID + tid] =
                    (s_buf[tid] + s_buf[tid + HID] + s_buf[tid + 2*HID] + s_buf[tid + 3*HID]) * s_inv[s];
        }
    }
}

extern "C" void kernel_launch(void* const* d_in, const int* in_sizes, int n_in,
                              void* d_out, int out_size) {
    const float* q = (const float*)d_in[0];
    const float* k = (const float*)d_in[1];
    const float* v = (const float*)d_in[2];
    float* out = (float*)d_out;

    swizzle_kb_kernel<<<NHEADS * NBLK_MAX * KSTEP * 32 / 256, 256>>>(k);
    swizzle_v_kernel<<<VFRAG_N / 256, 256>>>(v);

    cudaFuncSetAttribute(tree_attn_r14,
                         cudaFuncAttributeMaxDynamicSharedMemorySize, DYN_BYTES);

    dim3 grid(NTILES, NHEADS);
    tree_attn_r14<<<grid, NT, DYN_BYTES>>>(q, v, out);
}

// round 15
// speedup vs baseline: 1.1473x; 1.1473x over previous
#include <cuda_runtime.h>
#include <math_constants.h>

#define T_SRC   4096
#define T_DST   4096
#define HID     128
#define NHEADS  8
#define KTOP    128
#define TDENSE  1024
#define NT      512
#define QT      8
#define NW      (NT / 32)
#define NTILES  (T_DST / QT)
#define NBLK_MAX (T_SRC / 16)
#define NJBLK    (T_SRC / 8)
#define NDTILE   (HID / 16)

#define HPAD      264
#define CAND_CAP  1536
#define C2_CAP    256

#define W_SC    (QT * T_SRC)
#define W_Q     (QT * HID)
#define W_IDX   (QT * KTOP)
#define W_W     (QT * KTOP)
#define W_H3    (QT * HPAD)
#define W_CAND  (QT * CAND_CAP)
#define W_C2    (QT * C2_CAP)
#define W_EQ    KTOP
#define W_CTRL  64
#define W_SEL   (W_H3 + W_CAND + W_C2 + W_EQ + W_CTRL)
#define DYN_BYTES ((W_SC + W_Q + W_IDX + W_W + W_SEL) * 4)

#define KFRAG_N (NHEADS * NBLK_MAX * 16 * 32)
__device__ float4 g_kfrag[KFRAG_N];
#define VFRAG_N (NHEADS * NDTILE * NJBLK * 32)
__device__ float4 g_vfrag[VFRAG_N];

__device__ __forceinline__ unsigned fkey(float f) {
    unsigned b = __float_as_uint(f);
    return b ^ ((b & 0x80000000u) ? 0xFFFFFFFFu : 0x80000000u);
}
// inverse of fkey
__device__ __forceinline__ float unfkey(unsigned u) {
    unsigned b = u ^ ((u & 0x80000000u) ? 0x80000000u : 0xFFFFFFFFu);
    return __uint_as_float(b);
}

__device__ __forceinline__ unsigned tf32_hi_bits(float x) {
    return __float_as_uint(x) & 0xFFFFE000u;
}

__device__ __forceinline__ void mma_tf32(float& d0, float& d1, float& d2, float& d3,
                                         unsigned a0, unsigned a1, unsigned a2, unsigned a3,
                                         unsigned b0, unsigned b1) {
    asm volatile(
        "mma.sync.aligned.m16n8k8.row.col.f32.tf32.tf32.f32 "
        "{%0,%1,%2,%3}, {%4,%5,%6,%7}, {%8,%9}, {%0,%1,%2,%3};"
        : "+f"(d0), "+f"(d1), "+f"(d2), "+f"(d3)
        : "r"(a0), "r"(a1), "r"(a2), "r"(a3), "r"(b0), "r"(b1));
}

__device__ __forceinline__ float block_max(float v, float* sred) {
    #pragma unroll
    for (int o = 16; o; o >>= 1) v = fmaxf(v, __shfl_xor_sync(0xFFFFFFFFu, v, o));
    if ((threadIdx.x & 31) == 0) sred[threadIdx.x >> 5] = v;
    __syncthreads();
    if (threadIdx.x < 32) {
        float x = (threadIdx.x < NW) ? sred[threadIdx.x] : -CUDART_INF_F;
        #pragma unroll
        for (int o = 8; o; o >>= 1) x = fmaxf(x, __shfl_xor_sync(0xFFFFFFFFu, x, o));
        if (threadIdx.x == 0) sred[0] = x;
    }
    __syncthreads();
    v = sred[0];
    __syncthreads();
    return v;
}

__device__ __forceinline__ float block_sum(float v, float* sred) {
    #pragma unroll
    for (int o = 16; o; o >>= 1) v += __shfl_xor_sync(0xFFFFFFFFu, v, o);
    if ((threadIdx.x & 31) == 0) sred[threadIdx.x >> 5] = v;
    __syncthreads();
    if (threadIdx.x < 32) {
        float x = (threadIdx.x < NW) ? sred[threadIdx.x] : 0.0f;
        #pragma unroll
        for (int o = 8; o; o >>= 1) x += __shfl_xor_sync(0xFFFFFFFFu, x, o);
        if (threadIdx.x == 0) sred[0] = x;
    }
    __syncthreads();
    v = sred[0];
    __syncthreads();
    return v;
}

__global__ void swizzle_k_kernel(const float* __restrict__ k) {
    int t = blockIdx.x * blockDim.x + threadIdx.x;
    int lane = t & 31;
    int st   = (t >> 5) & 15;
    int blk  = (t >> 9) & (NBLK_MAX - 1);
    int h    = t >> 17;
    int g  = lane >> 2;
    int tg = lane & 3;
    int key = blk * 16 + g;
    int d   = st * 8 + tg;
    const float* kb = k + ((size_t)(h * T_SRC + key)) * HID + d;
    g_kfrag[t] = make_float4(kb[0], kb[8 * HID], kb[4], kb[8 * HID + 4]);
}

__global__ void swizzle_v_kernel(const float* __restrict__ v) {
    int t = blockIdx.x * blockDim.x + threadIdx.x;
    int lane = t & 31;
    int jb   = (t >> 5) & (NJBLK - 1);
    int dt   = (t >> 14) & (NDTILE - 1);
    int h    = t >> 17;
    int g  = lane >> 2;
    int tg = lane & 3;
    int d  = dt * 16 + g;
    int j  = jb * 8 + tg;
    const float* vb = v + (size_t)(h * T_SRC) * HID;
    g_vfrag[t] = make_float4(vb[(size_t)j * HID + d],
                             vb[(size_t)j * HID + d + 8],
                             vb[(size_t)(j + 4) * HID + d],
                             vb[(size_t)(j + 4) * HID + d + 8]);
}

__global__ __launch_bounds__(NT, 1)
void tree_attn_r15(const float* __restrict__ q,
                   const float* __restrict__ v,
                   float* __restrict__ out) {
    extern __shared__ char smem_raw[];
    float*    s_sc   = (float*)smem_raw;                     // [QT][T_SRC] (float | fkey)
    unsigned* s_su   = (unsigned*)smem_raw;                  // key view (sparse)
    float*    s_q    = s_sc + W_SC;
    int*      s_idx  = (int*)(s_q + W_Q);
    float*    s_w    = (float*)(s_idx + W_IDX);
    unsigned* s_h3   = (unsigned*)(s_w + W_W);
    int*      s_cand = (int*)(s_h3 + W_H3);
    int*      s_c2   = (int*)(s_cand + W_CAND);
    int*      s_eq   = (int*)(s_c2 + W_C2);
    unsigned* s_ctrl = (unsigned*)(s_eq + W_EQ);
    float*    s_buf  = (float*)s_h3;                         // [NT] (sparse AV)
    float*    s_av   = (float*)s_h3;                         // [2][8][128] (dense AV)
    unsigned* s_b3   = s_ctrl;
    unsigned* s_ngt3 = s_ctrl + 8;
    unsigned* s_gtc  = s_ctrl + 16;
    unsigned* s_cc   = s_ctrl + 24;
    unsigned* s_ovf  = s_ctrl + 32;
    unsigned* s_misc = s_ctrl + 40;
    float*    s_inv  = (float*)(s_ctrl + 48);
    __shared__ float s_redf[NW];

    const int tile = (NTILES - 1) - blockIdx.x;
    const int h    = blockIdx.y;
    const int tid  = threadIdx.x;
    const int wid  = tid >> 5;
    const int lane = tid & 31;
    const unsigned lmlt = (1u << lane) - 1u;
    const int qi0  = tile * QT;
    const int n_max = qi0 + QT;
    const bool sparse = (qi0 >= TDENSE);

    const float* vbase = v + (size_t)h * T_SRC * HID;

    for (int d = tid; d < QT * HID; d += NT)
        s_q[d] = q[((size_t)h * T_DST + qi0) * HID + d];
    if (sparse) {
        for (int i = tid; i < QT * HPAD; i += NT) s_h3[i] = 0u;
        if (tid < 8) { s_gtc[tid] = 0u; s_cc[tid] = 0u; s_ovf[tid] = 0u; }
    }
    __syncthreads();

    const int g  = lane >> 2;
    const int tg = lane & 3;
    unsigned bh[16][2], bl[16][2];
    #pragma unroll
    for (int st = 0; st < 16; st++) {
        float x0 = s_q[g * HID + st * 8 + tg];
        float x1 = s_q[g * HID + st * 8 + tg + 4];
        unsigned h0 = tf32_hi_bits(x0);
        unsigned h1 = tf32_hi_bits(x1);
        bh[st][0] = h0;
        bh[st][1] = h1;
        bl[st][0] = __float_as_uint(x0 - __uint_as_float(h0));
        bl[st][1] = __float_as_uint(x1 - __uint_as_float(h1));
    }

    // ---- scores via 3xTF32 mma; sparse tiles store fkey keys + fused histogram ----
    float mx[QT];
    #pragma unroll
    for (int s = 0; s < QT; s++) mx[s] = -CUDART_INF_F;

    const int nblk = (n_max + 15) >> 4;
    for (int blk = wid; blk < nblk; blk += NW) {
        float d0 = 0.f, d1 = 0.f, d2 = 0.f, d3 = 0.f;
        const float4* fk = g_kfrag + ((size_t)(h * NBLK_MAX + blk) * 16) * 32 + lane;
        #pragma unroll
        for (int st = 0; st < 16; st++) {
            float4 a4 = fk[st * 32];
            unsigned a0 = tf32_hi_bits(a4.x), a1 = tf32_hi_bits(a4.y);
            unsigned a2 = tf32_hi_bits(a4.z), a3 = tf32_hi_bits(a4.w);
            unsigned l0 = __float_as_uint(a4.x - __uint_as_float(a0));
            unsigned l1 = __float_as_uint(a4.y - __uint_as_float(a1));
            unsigned l2 = __float_as_uint(a4.z - __uint_as_float(a2));
            unsigned l3 = __float_as_uint(a4.w - __uint_as_float(a3));
            mma_tf32(d0, d1, d2, d3, a0, a1, a2, a3, bh[st][0], bh[st][1]);
            mma_tf32(d0, d1, d2, d3, a0, a1, a2, a3, bl[st][0], bl[st][1]);
            mma_tf32(d0, d1, d2, d3, l0, l1, l2, l3, bh[st][0], bh[st][1]);
        }
        const int kA = blk * 16 + g;
        const int kB = kA + 8;
        const int q0 = tg * 2;
        const int q1 = q0 + 1;
        float v0 = (kA <= qi0 + q0) ? d0 : -CUDART_INF_F;
        float v1 = (kA <= qi0 + q1) ? d1 : -CUDART_INF_F;
        float v2 = (kB <= qi0 + q0) ? d2 : -CUDART_INF_F;
        float v3 = (kB <= qi0 + q1) ? d3 : -CUDART_INF_F;
        mx[q0] = fmaxf(mx[q0], fmaxf(v0, v2));
        mx[q1] = fmaxf(mx[q1], fmaxf(v1, v3));
        if (sparse) {
            unsigned k0 = fkey(v0), k1 = fkey(v1), k2 = fkey(v2), k3 = fkey(v3);
            s_su[q0 * T_SRC + kA] = k0;
            s_su[q1 * T_SRC + kA] = k1;
            s_su[q0 * T_SRC + kB] = k2;
            s_su[q1 * T_SRC + kB] = k3;
            atomicAdd(&s_h3[q0 * HPAD + (k0 >> 24)], 1u);
            atomicAdd(&s_h3[q1 * HPAD + (k1 >> 24)], 1u);
            atomicAdd(&s_h3[q0 * HPAD + (k2 >> 24)], 1u);
            atomicAdd(&s_h3[q1 * HPAD + (k3 >> 24)], 1u);
        } else {
            s_sc[q0 * T_SRC + kA] = v0;
            s_sc[q1 * T_SRC + kA] = v1;
            s_sc[q0 * T_SRC + kB] = v2;
            s_sc[q1 * T_SRC + kB] = v3;
        }
    }
    __syncthreads();

    float m[QT];
    #pragma unroll
    for (int s = 0; s < QT; s++) m[s] = block_max(mx[s], s_redf);

    if (!sparse) {
        // ================= dense causal softmax =================
        float psum[QT];
        #pragma unroll
        for (int s = 0; s < QT; s++) psum[s] = 0.0f;
        for (int j = tid; j < n_max; j += NT) {
            #pragma unroll
            for (int s = 0; s < QT; s++) {
                float sc = s_sc[s * T_SRC + j];
                float e = (j <= qi0 + s) ? __expf(sc - m[s]) : 0.0f;
                s_sc[s * T_SRC + j] = e;
                psum[s] += e;
            }
        }
        #pragma unroll
        for (int s = 0; s < QT; s++) {
            float iv = 1.0f / block_sum(psum[s], s_redf);
            if (tid == 0) s_inv[s] = iv;
        }

        // ---- dense AV via 3xTF32 mma ----
        {
            const int dt = wid & 7;
            const int jh = wid >> 3;
            const int jchunks = n_max >> 3;
            float e0 = 0.f, e1 = 0.f, e2 = 0.f, e3 = 0.f;
            const float4* fv = g_vfrag + ((size_t)((h * NDTILE + dt) * NJBLK)) * 32 + lane;
            for (int c = jh; c < jchunks; c += 2) {
                float4 a4 = fv[c * 32];
                unsigned a0 = tf32_hi_bits(a4.x), a1 = tf32_hi_bits(a4.y);
                unsigned a2 = tf32_hi_bits(a4.z), a3 = tf32_hi_bits(a4.w);
                unsigned l0 = __float_as_uint(a4.x - __uint_as_float(a0));
                unsigned l1 = __float_as_uint(a4.y - __uint_as_float(a1));
                unsigned l2 = __float_as_uint(a4.z - __uint_as_float(a2));
                unsigned l3 = __float_as_uint(a4.w - __uint_as_float(a3));
                float p0 = s_sc[g * T_SRC + c * 8 + tg];
                float p1 = s_sc[g * T_SRC + c * 8 + tg + 4];
                unsigned ph0 = tf32_hi_bits(p0);
                unsigned ph1 = tf32_hi_bits(p1);
                unsigned pl0 = __float_as_uint(p0 - __uint_as_float(ph0));
                unsigned pl1 = __float_as_uint(p1 - __uint_as_float(ph1));
                mma_tf32(e0, e1, e2, e3, a0, a1, a2, a3, ph0, ph1);
                mma_tf32(e0, e1, e2, e3, l0, l1, l2, l3, ph0, ph1);
                mma_tf32(e0, e1, e2, e3, a0, a1, a2, a3, pl0, pl1);
            }
            int base = jh * 1024 + (tg * 2) * HID + dt * 16 + g;
            s_av[base]           = e0;
            s_av[base + HID]     = e1;
            s_av[base + 8]       = e2;
            s_av[base + HID + 8] = e3;
        }
        __syncthreads();
        #pragma unroll
        for (int i = tid; i < QT * HID; i += NT) {
            int qq = i >> 7;
            out[((size_t)h * T_DST + qi0 + qq) * HID + (i & (HID - 1))] =
                (s_av[i] + s_av[1024 + i]) * s_inv[qq];
        }
    } else {
        // ================= sparse: exact top-128 (keys in s_su) =================

        // ---- per-warp bin scan ----
        if (wid < QT) {
            const int s = wid;
            unsigned gg = 0;
            #pragma unroll
            for (int b = 0; b < 8; b++) gg += s_h3[s * HPAD + lane * 8 + b];
            unsigned run = gg;
            #pragma unroll
            for (int o = 1; o < 32; o <<= 1) {
                unsigned u = __shfl_down_sync(0xFFFFFFFFu, run, o);
                if (lane + o < 32) run += u;
            }
            unsigned S = run - gg;
            int found = (run >= KTOP && S < KTOP);
            unsigned blb = 0, acc2 = 0;
            if (found) {
                acc2 = S;
                #pragma unroll 1
                for (int b = 7; b >= 0; b--) {
                    unsigned c = s_h3[s * HPAD + lane * 8 + b];
                    if (acc2 + c >= KTOP) { blb = lane * 8 + b; break; }
                    acc2 += c;
                }
            }
            unsigned fmask = __ballot_sync(0xFFFFFFFFu, found);
            int flane = __ffs(fmask) - 1;
            blb  = __shfl_sync(0xFFFFFFFFu, blb, flane);
            acc2 = __shfl_sync(0xFFFFFFFFu, acc2, flane);
            if (lane == 0) { s_b3[s] = blb; s_ngt3[s] = acc2; }
        }
        __syncthreads();

        // ---- compact sweep: plain predicated atomics (hits are rare) ----
        {
            unsigned b3v[QT];
            #pragma unroll
            for (int s = 0; s < QT; s++) b3v[s] = s_b3[s];
            for (int j = tid; j < n_max; j += NT) {
                #pragma unroll
                for (int s = 0; s < QT; s++) {
                    unsigned bin = s_su[s * T_SRC + j] >> 24;
                    if (bin >= b3v[s]) {
                        if (bin > b3v[s]) {
                            unsigned p = atomicAdd(&s_gtc[s], 1u);
                            s_idx[s * KTOP + p] = j;
                        } else {
                            unsigned p = atomicAdd(&s_cc[s], 1u);
                            if (p < CAND_CAP) s_cand[s * CAND_CAP + p] = j;
                        }
                    }
                }
            }
        }
        __syncthreads();

        // ---- per-warp refinement (keys read directly) ----
        if (wid < QT) {
            const int s = wid;
            const unsigned* sc = s_su + s * T_SRC;
            int nc = (int)s_cc[s];
            unsigned ngt = s_ngt3[s];
            bool ok = (nc <= CAND_CAP);
            int cur = 0;
            int* lists[2] = { s_cand + s * CAND_CAP, s_c2 + s * C2_CAP };
            const int caps[2] = { CAND_CAP, C2_CAP };

            #pragma unroll 1
            for (int lvl = 2; lvl >= 0 && ok; lvl--) {
                const int shift = lvl * 8;
                for (int b = lane; b < 257; b += 32) s_h3[s * HPAD + b] = 0u;
                __syncwarp();
                const int rb = (nc + 31) & ~31;
                for (int i = lane; i < rb; i += 32) {
                    unsigned bin = 256u;
                    if (i < nc) bin = (sc[lists[cur][i]] >> shift) & 255u;
                    unsigned peers = __match_any_sync(0xFFFFFFFFu, bin);
                    if ((__ffs(peers) - 1) == lane)
                        s_h3[s * HPAD + bin] += (unsigned)__popc(peers);
                }
                __syncwarp();
                unsigned gg = 0;
                #pragma unroll
                for (int b = 0; b < 8; b++) gg += s_h3[s * HPAD + lane * 8 + b];
                unsigned run = gg;
                #pragma unroll
                for (int o = 1; o < 32; o <<= 1) {
                    unsigned u = __shfl_down_sync(0xFFFFFFFFu, run, o);
                    if (lane + o < 32) run += u;
                }
                unsigned S = run - gg;
                int found = (ngt + run >= KTOP && ngt + S < KTOP);
                unsigned blb = 0;
                if (found) {
                    unsigned acc2 = ngt + S;
                    #pragma unroll 1
                    for (int b = 7; b >= 0; b--) {
                        unsigned c = s_h3[s * HPAD + lane * 8 + b];
                        if (acc2 + c >= KTOP) { blb = lane * 8 + b; break; }
                        acc2 += c;
                    }
                }
                unsigned fmask = __ballot_sync(0xFFFFFFFFu, found);
                int flane = __ffs(fmask) - 1;
                blb = __shfl_sync(0xFFFFFFFFu, blb, flane);
                const int dst = cur ^ 1;
                int* dl = lists[dst];
                const int dcap = caps[dst];
                unsigned wg = ngt, we = 0;
                for (int i = lane; i < rb; i += 32) {
                    unsigned bin = 256u; int j = 0;
                    if (i < nc) { j = lists[cur][i]; bin = (sc[j] >> shift) & 255u; }
                    bool gt = (bin > blb) && (bin <= 255u);
                    bool eq = (bin == blb);
                    unsigned mg = __ballot_sync(0xFFFFFFFFu, gt);
                    unsigned me = __ballot_sync(0xFFFFFFFFu, eq);
                    if (gt) s_idx[s * KTOP + wg + __popc(mg & lmlt)] = j;
                    if (eq) {
                        unsigned p = we + __popc(me & lmlt);
                        if ((int)p < dcap) dl[p] = j;
                    }
                    wg += __popc(mg); we += __popc(me);
                }
                ngt = wg;
                nc = (int)we;
                cur = dst;
                if (nc > dcap) ok = false;
                __syncwarp();
            }
            if (ok) {
                const int need = KTOP - (int)ngt;
                const int* tl = lists[cur];
                for (int i = lane; i < nc; i += 32) {
                    int ji = tl[i];
                    int rank = 0;
                    for (int m2 = 0; m2 < nc; m2++) rank += (tl[m2] < ji);
                    if (rank < need) s_idx[s * KTOP + (int)ngt + rank] = ji;
                }
            } else if (lane == 0) {
                s_ovf[s] = 1u;
            }
        }
        __syncthreads();

        // ---- rare fallback: full 4-level radix on keys ----
        unsigned ovf_any = 0;
        #pragma unroll
        for (int s = 0; s < QT; s++) ovf_any |= s_ovf[s];
        if (ovf_any) {
            const int bound = ((n_max + NT - 1) / NT) * NT;
            #pragma unroll 1
            for (int s = 0; s < QT; s++) {
                if (!s_ovf[s]) continue;
                const unsigned* sc = s_su + s * T_SRC;
                unsigned prefix = 0, ngt = 0;
                #pragma unroll 1
                for (int level = 3; level >= 0; level--) {
                    for (int b = tid; b < 257; b += NT) s_h3[b] = 0u;
                    __syncthreads();
                    const unsigned shift = level * 8;
                    const unsigned pmask = (level == 3) ? 0u : (0xFFFFFFFFu << (shift + 8));
                    for (int j = tid; j < bound; j += NT) {
                        unsigned bin = 256u;
                        if (j < n_max) {
                            unsigned key = sc[j];
                            if ((key & pmask) == prefix) bin = (key >> shift) & 0xFFu;
                        }
                        unsigned peers = __match_any_sync(0xFFFFFFFFu, bin);
                        if ((__ffs(peers) - 1) == lane)
                            atomicAdd(&s_h3[bin], (unsigned)__popc(peers));
                    }
                    __syncthreads();
                    if (tid < 32) {
                        unsigned gg = 0;
                        #pragma unroll
                        for (int b = 0; b < 8; b++) gg += s_h3[tid * 8 + b];
                        unsigned run = gg;
                        #pragma unroll
                        for (int o = 1; o < 32; o <<= 1) {
                            unsigned u = __shfl_down_sync(0xFFFFFFFFu, run, o);
                            if (tid + o < 32) run += u;
                        }
                        unsigned S = run - gg;
                        if (ngt + run >= KTOP && ngt + S < KTOP) {
                            unsigned acc2 = ngt + S;
                            #pragma unroll 1
                            for (int b = 7; b >= 0; b--) {
                                unsigned c = s_h3[tid * 8 + b];
                                if (acc2 + c >= KTOP) {
                                    s_misc[0] = prefix | ((unsigned)(tid * 8 + b) << shift);
                                    s_misc[1] = acc2;
                                    break;
                                }
                                acc2 += c;
                            }
                        }
                    }
                    __syncthreads();
                    prefix = s_misc[0];
                    ngt = s_misc[1];
                    __syncthreads();
                }
                const unsigned t_key = prefix;
                if (tid == 0) { s_misc[2] = 0u; s_misc[3] = 0u; }
                __syncthreads();
                for (int j = tid; j < n_max; j += NT) {
                    unsigned key = sc[j];
                    if (key > t_key) {
                        unsigned p = atomicAdd(&s_misc[2], 1u);
                        s_idx[s * KTOP + p] = j;
                    } else if (key == t_key) {
                        unsigned p = atomicAdd(&s_misc[3], 1u);
                        if (p < KTOP) s_eq[p] = j;
                    }
                }
                __syncthreads();
                const int neq = (int)s_misc[3];
                const int need = KTOP - (int)ngt;
                if (need < neq && tid == 0) {
                    int c = (neq < KTOP) ? neq : KTOP;
                    for (int a = 0; a < need; a++) {
                        int mb = a;
                        for (int b = a + 1; b < c; b++)
                            if (s_eq[b] < s_eq[mb]) mb = b;
                        int t2 = s_eq[a]; s_eq[a] = s_eq[mb]; s_eq[mb] = t2;
                    }
                }
                __syncthreads();
                for (int a = tid; a < need; a += NT) s_idx[s * KTOP + (int)ngt + a] = s_eq[a];
                __syncthreads();
            }
        }

        // ---- per-warp softmax weights (un-fkey the selected keys) ----
        if (wid < QT) {
            const int s = wid;
            float psum = 0.0f;
            #pragma unroll
            for (int i = 0; i < KTOP / 32; i++) {
                int a = lane + i * 32;
                float sc = unfkey(s_su[s * T_SRC + s_idx[s * KTOP + a]]);
                float e = __expf(sc - m[s]);
                s_w[s * KTOP + a] = e;
                psum += e;
            }
            #pragma unroll
            for (int o = 16; o; o >>= 1) psum += __shfl_xor_sync(0xFFFFFFFFu, psum, o);
            if (lane == 0) s_inv[s] = 1.0f / psum;
        }
        __syncthreads();

        // ---- AV over gathered rows ----
        const int d  = tid & (HID - 1);
        const int qr = tid >> 7;
        float acc[QT];
        #pragma unroll
        for (int s = 0; s < QT; s++) acc[s] = 0.0f;
        for (int a = qr; a < KTOP; a += 4) {
            #pragma unroll
            for (int s = 0; s < QT; s++) {
                int j = s_idx[s * KTOP + a];
                acc[s] = fmaf(s_w[s * KTOP + a], vbase[(size_t)j * HID + d], acc[s]);
            }
        }
        #pragma unroll
        for (int s = 0; s < QT; s++) {
            __syncthreads();
            s_buf[tid] = acc[s];
            __syncthreads();
            if (tid < HID)
                out[((size_t)h * T_DST + qi0 + s) * HID + tid] =
                    (s_buf[tid] + s_buf[tid + HID] + s_buf[tid + 2*HID] + s_buf[tid + 3*HID]) * s_inv[s];
        }
    }
}

extern "C" void kernel_launch(void* const* d_in, const int* in_sizes, int n_in,
                              void* d_out, int out_size) {
    const float* q = (const float*)d_in[0];
    const float* k = (const float*)d_in[1];
    const float* v = (const float*)d_in[2];
    float* out = (float*)d_out;

    swizzle_k_kernel<<<KFRAG_N / 256, 256>>>(k);
    swizzle_v_kernel<<<VFRAG_N / 256, 256>>>(v);

    cudaFuncSetAttribute(tree_attn_r15,
                         cudaFuncAttributeMaxDynamicSharedMemorySize, DYN_BYTES);

    dim3 grid(NTILES, NHEADS);
    tree_attn_r15<<<grid, NT, DYN_BYTES>>>(q, v, out);
}

// round 16
// speedup vs baseline: 1.2227x; 1.0658x over previous
#include <cuda_runtime.h>
#include <math_constants.h>

#define T_SRC   4096
#define T_DST   4096
#define HID     128
#define NHEADS  8
#define KTOP    128
#define TDENSE  1024
#define NT      512
#define QT      8
#define NW      (NT / 32)
#define NTILES  (T_DST / QT)
#define NBLK_MAX (T_SRC / 16)
#define NJBLK    (T_SRC / 8)
#define NDTILE   (HID / 16)

#define HPAD      264
#define CAND_CAP  1536
#define C2_CAP    256

#define W_SC    (QT * T_SRC)
#define W_Q     (QT * HID)
#define W_IDX   (QT * KTOP)
#define W_W     (QT * KTOP)
#define W_H3    (QT * HPAD)
#define W_CAND  (QT * CAND_CAP)
#define W_C2    (QT * C2_CAP)
#define W_EQ    KTOP
#define W_CTRL  64
#define W_SEL   (W_H3 + W_CAND + W_C2 + W_EQ + W_CTRL)
#define DYN_BYTES ((W_SC + W_Q + W_IDX + W_W + W_SEL) * 4)

#define KFRAG_N (NHEADS * NBLK_MAX * 16 * 32)
__device__ float4 g_kfrag[KFRAG_N];
#define VFRAG_N (NHEADS * NDTILE * NJBLK * 32)
__device__ float4 g_vfrag[VFRAG_N];

__device__ __forceinline__ unsigned fkey(float f) {
    unsigned b = __float_as_uint(f);
    return b ^ ((b & 0x80000000u) ? 0xFFFFFFFFu : 0x80000000u);
}
__device__ __forceinline__ float unfkey(unsigned u) {
    unsigned b = u ^ ((u & 0x80000000u) ? 0x80000000u : 0xFFFFFFFFu);
    return __uint_as_float(b);
}

__device__ __forceinline__ unsigned tf32_hi_bits(float x) {
    return __float_as_uint(x) & 0xFFFFE000u;
}

__device__ __forceinline__ void mma_tf32(float& d0, float& d1, float& d2, float& d3,
                                         unsigned a0, unsigned a1, unsigned a2, unsigned a3,
                                         unsigned b0, unsigned b1) {
    asm volatile(
        "mma.sync.aligned.m16n8k8.row.col.f32.tf32.tf32.f32 "
        "{%0,%1,%2,%3}, {%4,%5,%6,%7}, {%8,%9}, {%0,%1,%2,%3};"
        : "+f"(d0), "+f"(d1), "+f"(d2), "+f"(d3)
        : "r"(a0), "r"(a1), "r"(a2), "r"(a3), "r"(b0), "r"(b1));
}

__device__ __forceinline__ float block_max(float v, float* sred) {
    #pragma unroll
    for (int o = 16; o; o >>= 1) v = fmaxf(v, __shfl_xor_sync(0xFFFFFFFFu, v, o));
    if ((threadIdx.x & 31) == 0) sred[threadIdx.x >> 5] = v;
    __syncthreads();
    if (threadIdx.x < 32) {
        float x = (threadIdx.x < NW) ? sred[threadIdx.x] : -CUDART_INF_F;
        #pragma unroll
        for (int o = 8; o; o >>= 1) x = fmaxf(x, __shfl_xor_sync(0xFFFFFFFFu, x, o));
        if (threadIdx.x == 0) sred[0] = x;
    }
    __syncthreads();
    v = sred[0];
    __syncthreads();
    return v;
}

__device__ __forceinline__ float block_sum(float v, float* sred) {
    #pragma unroll
    for (int o = 16; o; o >>= 1) v += __shfl_xor_sync(0xFFFFFFFFu, v, o);
    if ((threadIdx.x & 31) == 0) sred[threadIdx.x >> 5] = v;
    __syncthreads();
    if (threadIdx.x < 32) {
        float x = (threadIdx.x < NW) ? sred[threadIdx.x] : 0.0f;
        #pragma unroll
        for (int o = 8; o; o >>= 1) x += __shfl_xor_sync(0xFFFFFFFFu, x, o);
        if (threadIdx.x == 0) sred[0] = x;
    }
    __syncthreads();
    v = sred[0];
    __syncthreads();
    return v;
}

__global__ void swizzle_k_kernel(const float* __restrict__ k) {
    int t = blockIdx.x * blockDim.x + threadIdx.x;
    int lane = t & 31;
    int st   = (t >> 5) & 15;
    int blk  = (t >> 9) & (NBLK_MAX - 1);
    int h    = t >> 17;
    int g  = lane >> 2;
    int tg = lane & 3;
    int key = blk * 16 + g;
    int d   = st * 8 + tg;
    const float* kb = k + ((size_t)(h * T_SRC + key)) * HID + d;
    g_kfrag[t] = make_float4(kb[0], kb[8 * HID], kb[4], kb[8 * HID + 4]);
}

__global__ void swizzle_v_kernel(const float* __restrict__ v) {
    int t = blockIdx.x * blockDim.x + threadIdx.x;
    int lane = t & 31;
    int jb   = (t >> 5) & (NJBLK - 1);
    int dt   = (t >> 14) & (NDTILE - 1);
    int h    = t >> 17;
    int g  = lane >> 2;
    int tg = lane & 3;
    int d  = dt * 16 + g;
    int j  = jb * 8 + tg;
    const float* vb = v + (size_t)(h * T_SRC) * HID;
    g_vfrag[t] = make_float4(vb[(size_t)j * HID + d],
                             vb[(size_t)j * HID + d + 8],
                             vb[(size_t)(j + 4) * HID + d],
                             vb[(size_t)(j + 4) * HID + d + 8]);
}

__global__ __launch_bounds__(NT, 1)
void tree_attn_r16(const float* __restrict__ q,
                   const float* __restrict__ v,
                   float* __restrict__ out) {
    extern __shared__ char smem_raw[];
    float*    s_sc   = (float*)smem_raw;                     // [QT][T_SRC] (float | fkey)
    unsigned* s_su   = (unsigned*)smem_raw;                  // key view (sparse)
    float*    s_q    = s_sc + W_SC;
    int*      s_idx  = (int*)(s_q + W_Q);
    float*    s_w    = (float*)(s_idx + W_IDX);
    unsigned* s_h3   = (unsigned*)(s_w + W_W);
    int*      s_cand = (int*)(s_h3 + W_H3);
    int*      s_c2   = (int*)(s_cand + W_CAND);
    int*      s_eq   = (int*)(s_c2 + W_C2);
    unsigned* s_ctrl = (unsigned*)(s_eq + W_EQ);
    float*    s_av   = (float*)s_h3;                         // [2][8][128] (AV partials)
    unsigned* s_b3   = s_ctrl;
    unsigned* s_ngt3 = s_ctrl + 8;
    unsigned* s_gtc  = s_ctrl + 16;
    unsigned* s_cc   = s_ctrl + 24;
    unsigned* s_ovf  = s_ctrl + 32;
    unsigned* s_misc = s_ctrl + 40;
    float*    s_inv  = (float*)(s_ctrl + 48);
    __shared__ float s_redf[NW];

    const int tile = (NTILES - 1) - blockIdx.x;
    const int h    = blockIdx.y;
    const int tid  = threadIdx.x;
    const int wid  = tid >> 5;
    const int lane = tid & 31;
    const unsigned lmlt = (1u << lane) - 1u;
    const int qi0  = tile * QT;
    const int n_max = qi0 + QT;
    const bool sparse = (qi0 >= TDENSE);

    const float* vbase = v + (size_t)h * T_SRC * HID;

    for (int d = tid; d < QT * HID; d += NT)
        s_q[d] = q[((size_t)h * T_DST + qi0) * HID + d];
    if (sparse) {
        for (int i = tid; i < QT * HPAD; i += NT) s_h3[i] = 0u;
        if (tid < 8) { s_gtc[tid] = 0u; s_cc[tid] = 0u; s_ovf[tid] = 0u; }
    }
    __syncthreads();

    const int g  = lane >> 2;
    const int tg = lane & 3;
    unsigned bh[16][2], bl[16][2];
    #pragma unroll
    for (int st = 0; st < 16; st++) {
        float x0 = s_q[g * HID + st * 8 + tg];
        float x1 = s_q[g * HID + st * 8 + tg + 4];
        unsigned h0 = tf32_hi_bits(x0);
        unsigned h1 = tf32_hi_bits(x1);
        bh[st][0] = h0;
        bh[st][1] = h1;
        bl[st][0] = __float_as_uint(x0 - __uint_as_float(h0));
        bl[st][1] = __float_as_uint(x1 - __uint_as_float(h1));
    }

    // ---- scores via 3xTF32 mma; sparse stores fkey keys + fused histogram ----
    float mx[QT];
    #pragma unroll
    for (int s = 0; s < QT; s++) mx[s] = -CUDART_INF_F;

    const int nblk = (n_max + 15) >> 4;
    for (int blk = wid; blk < nblk; blk += NW) {
        float d0 = 0.f, d1 = 0.f, d2 = 0.f, d3 = 0.f;
        const float4* fk = g_kfrag + ((size_t)(h * NBLK_MAX + blk) * 16) * 32 + lane;
        #pragma unroll
        for (int st = 0; st < 16; st++) {
            float4 a4 = fk[st * 32];
            unsigned a0 = tf32_hi_bits(a4.x), a1 = tf32_hi_bits(a4.y);
            unsigned a2 = tf32_hi_bits(a4.z), a3 = tf32_hi_bits(a4.w);
            unsigned l0 = __float_as_uint(a4.x - __uint_as_float(a0));
            unsigned l1 = __float_as_uint(a4.y - __uint_as_float(a1));
            unsigned l2 = __float_as_uint(a4.z - __uint_as_float(a2));
            unsigned l3 = __float_as_uint(a4.w - __uint_as_float(a3));
            mma_tf32(d0, d1, d2, d3, a0, a1, a2, a3, bh[st][0], bh[st][1]);
            mma_tf32(d0, d1, d2, d3, a0, a1, a2, a3, bl[st][0], bl[st][1]);
            mma_tf32(d0, d1, d2, d3, l0, l1, l2, l3, bh[st][0], bh[st][1]);
        }
        const int kA = blk * 16 + g;
        const int kB = kA + 8;
        const int q0 = tg * 2;
        const int q1 = q0 + 1;
        float v0 = (kA <= qi0 + q0) ? d0 : -CUDART_INF_F;
        float v1 = (kA <= qi0 + q1) ? d1 : -CUDART_INF_F;
        float v2 = (kB <= qi0 + q0) ? d2 : -CUDART_INF_F;
        float v3 = (kB <= qi0 + q1) ? d3 : -CUDART_INF_F;
        mx[q0] = fmaxf(mx[q0], fmaxf(v0, v2));
        mx[q1] = fmaxf(mx[q1], fmaxf(v1, v3));
        if (sparse) {
            unsigned k0 = fkey(v0), k1 = fkey(v1), k2 = fkey(v2), k3 = fkey(v3);
            s_su[q0 * T_SRC + kA] = k0;
            s_su[q1 * T_SRC + kA] = k1;
            s_su[q0 * T_SRC + kB] = k2;
            s_su[q1 * T_SRC + kB] = k3;
            atomicAdd(&s_h3[q0 * HPAD + (k0 >> 24)], 1u);
            atomicAdd(&s_h3[q1 * HPAD + (k1 >> 24)], 1u);
            atomicAdd(&s_h3[q0 * HPAD + (k2 >> 24)], 1u);
            atomicAdd(&s_h3[q1 * HPAD + (k3 >> 24)], 1u);
        } else {
            s_sc[q0 * T_SRC + kA] = v0;
            s_sc[q1 * T_SRC + kA] = v1;
            s_sc[q0 * T_SRC + kB] = v2;
            s_sc[q1 * T_SRC + kB] = v3;
        }
    }
    __syncthreads();

    float m[QT];
    #pragma unroll
    for (int s = 0; s < QT; s++) m[s] = block_max(mx[s], s_redf);

    if (!sparse) {
        // ================= dense causal softmax =================
        float psum[QT];
        #pragma unroll
        for (int s = 0; s < QT; s++) psum[s] = 0.0f;
        for (int j = tid; j < n_max; j += NT) {
            #pragma unroll
            for (int s = 0; s < QT; s++) {
                float sc = s_sc[s * T_SRC + j];
                float e = (j <= qi0 + s) ? __expf(sc - m[s]) : 0.0f;
                s_sc[s * T_SRC + j] = e;
                psum[s] += e;
            }
        }
        #pragma unroll
        for (int s = 0; s < QT; s++) {
            float iv = 1.0f / block_sum(psum[s], s_redf);
            if (tid == 0) s_inv[s] = iv;
        }

        // ---- dense AV via 3xTF32 mma ----
        {
            const int dt = wid & 7;
            const int jh = wid >> 3;
            const int jchunks = n_max >> 3;
            float e0 = 0.f, e1 = 0.f, e2 = 0.f, e3 = 0.f;
            const float4* fv = g_vfrag + ((size_t)((h * NDTILE + dt) * NJBLK)) * 32 + lane;
            for (int c = jh; c < jchunks; c += 2) {
                float4 a4 = fv[c * 32];
                unsigned a0 = tf32_hi_bits(a4.x), a1 = tf32_hi_bits(a4.y);
                unsigned a2 = tf32_hi_bits(a4.z), a3 = tf32_hi_bits(a4.w);
                unsigned l0 = __float_as_uint(a4.x - __uint_as_float(a0));
                unsigned l1 = __float_as_uint(a4.y - __uint_as_float(a1));
                unsigned l2 = __float_as_uint(a4.z - __uint_as_float(a2));
                unsigned l3 = __float_as_uint(a4.w - __uint_as_float(a3));
                float p0 = s_sc[g * T_SRC + c * 8 + tg];
                float p1 = s_sc[g * T_SRC + c * 8 + tg + 4];
                unsigned ph0 = tf32_hi_bits(p0);
                unsigned ph1 = tf32_hi_bits(p1);
                unsigned pl0 = __float_as_uint(p0 - __uint_as_float(ph0));
                unsigned pl1 = __float_as_uint(p1 - __uint_as_float(ph1));
                mma_tf32(e0, e1, e2, e3, a0, a1, a2, a3, ph0, ph1);
                mma_tf32(e0, e1, e2, e3, l0, l1, l2, l3, ph0, ph1);
                mma_tf32(e0, e1, e2, e3, a0, a1, a2, a3, pl0, pl1);
            }
            int base = jh * 1024 + (tg * 2) * HID + dt * 16 + g;
            s_av[base]           = e0;
            s_av[base + HID]     = e1;
            s_av[base + 8]       = e2;
            s_av[base + HID + 8] = e3;
        }
        __syncthreads();
        #pragma unroll
        for (int i = tid; i < QT * HID; i += NT) {
            int qq = i >> 7;
            out[((size_t)h * T_DST + qi0 + qq) * HID + (i & (HID - 1))] =
                (s_av[i] + s_av[1024 + i]) * s_inv[qq];
        }
    } else {
        // ================= sparse: exact top-128 (keys in s_su) =================

        // ---- per-warp bin scan ----
        if (wid < QT) {
            const int s = wid;
            unsigned gg = 0;
            #pragma unroll
            for (int b = 0; b < 8; b++) gg += s_h3[s * HPAD + lane * 8 + b];
            unsigned run = gg;
            #pragma unroll
            for (int o = 1; o < 32; o <<= 1) {
                unsigned u = __shfl_down_sync(0xFFFFFFFFu, run, o);
                if (lane + o < 32) run += u;
            }
            unsigned S = run - gg;
            int found = (run >= KTOP && S < KTOP);
            unsigned blb = 0, acc2 = 0;
            if (found) {
                acc2 = S;
                #pragma unroll 1
                for (int b = 7; b >= 0; b--) {
                    unsigned c = s_h3[s * HPAD + lane * 8 + b];
                    if (acc2 + c >= KTOP) { blb = lane * 8 + b; break; }
                    acc2 += c;
                }
            }
            unsigned fmask = __ballot_sync(0xFFFFFFFFu, found);
            int flane = __ffs(fmask) - 1;
            blb  = __shfl_sync(0xFFFFFFFFu, blb, flane);
            acc2 = __shfl_sync(0xFFFFFFFFu, acc2, flane);
            if (lane == 0) { s_b3[s] = blb; s_ngt3[s] = acc2; }
        }
        __syncthreads();

        // ---- compact sweep: plain predicated atomics ----
        {
            unsigned b3v[QT];
            #pragma unroll
            for (int s = 0; s < QT; s++) b3v[s] = s_b3[s];
            for (int j = tid; j < n_max; j += NT) {
                #pragma unroll
                for (int s = 0; s < QT; s++) {
                    unsigned bin = s_su[s * T_SRC + j] >> 24;
                    if (bin >= b3v[s]) {
                        if (bin > b3v[s]) {
                            unsigned p = atomicAdd(&s_gtc[s], 1u);
                            s_idx[s * KTOP + p] = j;
                        } else {
                            unsigned p = atomicAdd(&s_cc[s], 1u);
                            if (p < CAND_CAP) s_cand[s * CAND_CAP + p] = j;
                        }
                    }
                }
            }
        }
        __syncthreads();

        // ---- per-warp refinement ----
        if (wid < QT) {
            const int s = wid;
            const unsigned* sc = s_su + s * T_SRC;
            int nc = (int)s_cc[s];
            unsigned ngt = s_ngt3[s];
            bool ok = (nc <= CAND_CAP);
            int cur = 0;
            int* lists[2] = { s_cand + s * CAND_CAP, s_c2 + s * C2_CAP };
            const int caps[2] = { CAND_CAP, C2_CAP };

            #pragma unroll 1
            for (int lvl = 2; lvl >= 0 && ok; lvl--) {
                const int shift = lvl * 8;
                for (int b = lane; b < 257; b += 32) s_h3[s * HPAD + b] = 0u;
                __syncwarp();
                const int rb = (nc + 31) & ~31;
                for (int i = lane; i < rb; i += 32) {
                    unsigned bin = 256u;
                    if (i < nc) bin = (sc[lists[cur][i]] >> shift) & 255u;
                    unsigned peers = __match_any_sync(0xFFFFFFFFu, bin);
                    if ((__ffs(peers) - 1) == lane)
                        s_h3[s * HPAD + bin] += (unsigned)__popc(peers);
                }
                __syncwarp();
                unsigned gg = 0;
                #pragma unroll
                for (int b = 0; b < 8; b++) gg += s_h3[s * HPAD + lane * 8 + b];
                unsigned run = gg;
                #pragma unroll
                for (int o = 1; o < 32; o <<= 1) {
                    unsigned u = __shfl_down_sync(0xFFFFFFFFu, run, o);
                    if (lane + o < 32) run += u;
                }
                unsigned S = run - gg;
                int found = (ngt + run >= KTOP && ngt + S < KTOP);
                unsigned blb = 0;
                if (found) {
                    unsigned acc2 = ngt + S;
                    #pragma unroll 1
                    for (int b = 7; b >= 0; b--) {
                        unsigned c = s_h3[s * HPAD + lane * 8 + b];
                        if (acc2 + c >= KTOP) { blb = lane * 8 + b; break; }
                        acc2 += c;
                    }
                }
                unsigned fmask = __ballot_sync(0xFFFFFFFFu, found);
                int flane = __ffs(fmask) - 1;
                blb = __shfl_sync(0xFFFFFFFFu, blb, flane);
                const int dst = cur ^ 1;
                int* dl = lists[dst];
                const int dcap = caps[dst];
                unsigned wg = ngt, we = 0;
                for (int i = lane; i < rb; i += 32) {
                    unsigned bin = 256u; int j = 0;
                    if (i < nc) { j = lists[cur][i]; bin = (sc[j] >> shift) & 255u; }
                    bool gt = (bin > blb) && (bin <= 255u);
                    bool eq = (bin == blb);
                    unsigned mg = __ballot_sync(0xFFFFFFFFu, gt);
                    unsigned me = __ballot_sync(0xFFFFFFFFu, eq);
                    if (gt) s_idx[s * KTOP + wg + __popc(mg & lmlt)] = j;
                    if (eq) {
                        unsigned p = we + __popc(me & lmlt);
                        if ((int)p < dcap) dl[p] = j;
                    }
                    wg += __popc(mg); we += __popc(me);
                }
                ngt = wg;
                nc = (int)we;
                cur = dst;
                if (nc > dcap) ok = false;
                __syncwarp();
            }
            if (ok) {
                const int need = KTOP - (int)ngt;
                const int* tl = lists[cur];
                for (int i = lane; i < nc; i += 32) {
                    int ji = tl[i];
                    int rank = 0;
                    for (int m2 = 0; m2 < nc; m2++) rank += (tl[m2] < ji);
                    if (rank < need) s_idx[s * KTOP + (int)ngt + rank] = ji;
                }
            } else if (lane == 0) {
                s_ovf[s] = 1u;
            }
        }
        __syncthreads();

        // ---- rare fallback: full 4-level radix on keys ----
        unsigned ovf_any = 0;
        #pragma unroll
        for (int s = 0; s < QT; s++) ovf_any |= s_ovf[s];
        if (ovf_any) {
            const int bound = ((n_max + NT - 1) / NT) * NT;
            #pragma unroll 1
            for (int s = 0; s < QT; s++) {
                if (!s_ovf[s]) continue;
                const unsigned* sc = s_su + s * T_SRC;
                unsigned prefix = 0, ngt = 0;
                #pragma unroll 1
                for (int level = 3; level >= 0; level--) {
                    for (int b = tid; b < 257; b += NT) s_h3[b] = 0u;
                    __syncthreads();
                    const unsigned shift = level * 8;
                    const unsigned pmask = (level == 3) ? 0u : (0xFFFFFFFFu << (shift + 8));
                    for (int j = tid; j < bound; j += NT) {
                        unsigned bin = 256u;
                        if (j < n_max) {
                            unsigned key = sc[j];
                            if ((key & pmask) == prefix) bin = (key >> shift) & 0xFFu;
                        }
                        unsigned peers = __match_any_sync(0xFFFFFFFFu, bin);
                        if ((__ffs(peers) - 1) == lane)
                            atomicAdd(&s_h3[bin], (unsigned)__popc(peers));
                    }
                    __syncthreads();
                    if (tid < 32) {
                        unsigned gg = 0;
                        #pragma unroll
                        for (int b = 0; b < 8; b++) gg += s_h3[tid * 8 + b];
                        unsigned run = gg;
                        #pragma unroll
                        for (int o = 1; o < 32; o <<= 1) {
                            unsigned u = __shfl_down_sync(0xFFFFFFFFu, run, o);
                            if (tid + o < 32) run += u;
                        }
                        unsigned S = run - gg;
                        if (ngt + run >= KTOP && ngt + S < KTOP) {
                            unsigned acc2 = ngt + S;
                            #pragma unroll 1
                            for (int b = 7; b >= 0; b--) {
                                unsigned c = s_h3[tid * 8 + b];
                                if (acc2 + c >= KTOP) {
                                    s_misc[0] = prefix | ((unsigned)(tid * 8 + b) << shift);
                                    s_misc[1] = acc2;
                                    break;
                                }
                                acc2 += c;
                            }
                        }
                    }
                    __syncthreads();
                    prefix = s_misc[0];
                    ngt = s_misc[1];
                    __syncthreads();
                }
                const unsigned t_key = prefix;
                if (tid == 0) { s_misc[2] = 0u; s_misc[3] = 0u; }
                __syncthreads();
                for (int j = tid; j < n_max; j += NT) {
                    unsigned key = sc[j];
                    if (key > t_key) {
                        unsigned p = atomicAdd(&s_misc[2], 1u);
                        s_idx[s * KTOP + p] = j;
                    } else if (key == t_key) {
                        unsigned p = atomicAdd(&s_misc[3], 1u);
                        if (p < KTOP) s_eq[p] = j;
                    }
                }
                __syncthreads();
                const int neq = (int)s_misc[3];
                const int need = KTOP - (int)ngt;
                if (need < neq && tid == 0) {
                    int c = (neq < KTOP) ? neq : KTOP;
                    for (int a = 0; a < need; a++) {
                        int mb = a;
                        for (int b = a + 1; b < c; b++)
                            if (s_eq[b] < s_eq[mb]) mb = b;
                        int t2 = s_eq[a]; s_eq[a] = s_eq[mb]; s_eq[mb] = t2;
                    }
                }
                __syncthreads();
                for (int a = tid; a < need; a += NT) s_idx[s * KTOP + (int)ngt + a] = s_eq[a];
                __syncthreads();
            }
        }

        // ---- per-warp softmax weights ----
        if (wid < QT) {
            const int s = wid;
            float psum = 0.0f;
            #pragma unroll
            for (int i = 0; i < KTOP / 32; i++) {
                int a = lane + i * 32;
                float sc = unfkey(s_su[s * T_SRC + s_idx[s * KTOP + a]]);
                float e = __expf(sc - m[s]);
                s_w[s * KTOP + a] = e;
                psum += e;
            }
            #pragma unroll
            for (int o = 16; o; o >>= 1) psum += __shfl_xor_sync(0xFFFFFFFFu, psum, o);
            if (lane == 0) s_inv[s] = 1.0f / psum;
        }
        __syncthreads();

        // ---- sparse AV: warp per (query, row-half), float4 lanes ----
        {
            const int s  = wid & 7;     // query
            const int jh = wid >> 3;    // row half 0..1
            const int* isrc = s_idx + s * KTOP;
            const float* wsrc = s_w + s * KTOP;
            float4 acc4 = make_float4(0.f, 0.f, 0.f, 0.f);
            const int a0 = jh * 64;
            #pragma unroll 2
            for (int a = a0; a < a0 + 64; a += 2) {
                int j0 = isrc[a];
                int j1 = isrc[a + 1];
                float w0 = wsrc[a];
                float w1 = wsrc[a + 1];
                float4 v0 = *(const float4*)(vbase + (size_t)j0 * HID + lane * 4);
                float4 v1 = *(const float4*)(vbase + (size_t)j1 * HID + lane * 4);
                acc4.x = fmaf(w0, v0.x, acc4.x);
                acc4.y = fmaf(w0, v0.y, acc4.y);
                acc4.z = fmaf(w0, v0.z, acc4.z);
                acc4.w = fmaf(w0, v0.w, acc4.w);
                acc4.x = fmaf(w1, v1.x, acc4.x);
                acc4.y = fmaf(w1, v1.y, acc4.y);
                acc4.z = fmaf(w1, v1.z, acc4.z);
                acc4.w = fmaf(w1, v1.w, acc4.w);
            }
            ((float4*)(s_av + jh * 1024 + s * HID))[lane] = acc4;
        }
        __syncthreads();
        #pragma unroll
        for (int i = tid; i < QT * HID; i += NT) {
            int qq = i >> 7;
            out[((size_t)h * T_DST + qi0 + qq) * HID + (i & (HID - 1))] =
                (s_av[i] + s_av[1024 + i]) * s_inv[qq];
        }
    }
}

extern "C" void kernel_launch(void* const* d_in, const int* in_sizes, int n_in,
                              void* d_out, int out_size) {
    const float* q = (const float*)d_in[0];
    const float* k = (const float*)d_in[1];
    const float* v = (const float*)d_in[2];
    float* out = (float*)d_out;

    swizzle_k_kernel<<<KFRAG_N / 256, 256>>>(k);
    swizzle_v_kernel<<<VFRAG_N / 256, 256>>>(v);

    cudaFuncSetAttribute(tree_attn_r16,
                         cudaFuncAttributeMaxDynamicSharedMemorySize, DYN_BYTES);

    dim3 grid(NTILES, NHEADS);
    tree_attn_r16<<<grid, NT, DYN_BYTES>>>(q, v, out);
}

// round 17
// speedup vs baseline: 1.2252x; 1.0020x over previous
#include <cuda_runtime.h>
#include <math_constants.h>

#define T_SRC   4096
#define T_DST   4096
#define HID     128
#define NHEADS  8
#define KTOP    128
#define TDENSE  1024
#define NT      512
#define QT      8
#define NW      (NT / 32)
#define NTILES  (T_DST / QT)
#define NBLK_MAX (T_SRC / 16)
#define NJBLK    (T_SRC / 8)
#define NDTILE   (HID / 16)

#define HPAD      264
#define CAND_CAP  1536
#define C2_CAP    256

#define W_SC    (QT * T_SRC)
#define W_Q     (QT * HID)
#define W_IDX   (QT * KTOP)
#define W_W     (QT * KTOP)
#define W_H3    (QT * HPAD)
#define W_CAND  (QT * CAND_CAP)
#define W_C2    (QT * C2_CAP)
#define W_EQ    KTOP
#define W_CTRL  64
#define W_SEL   (W_H3 + W_CAND + W_C2 + W_EQ + W_CTRL)
#define DYN_BYTES ((W_SC + W_Q + W_IDX + W_W + W_SEL) * 4)

#define KFRAG_N (NHEADS * NBLK_MAX * 16 * 32)
__device__ float4 g_kfrag[KFRAG_N];
#define VFRAG_N (NHEADS * NDTILE * NJBLK * 32)
__device__ float4 g_vfrag[VFRAG_N];

__device__ __forceinline__ unsigned fkey(float f) {
    unsigned b = __float_as_uint(f);
    return b ^ ((b & 0x80000000u) ? 0xFFFFFFFFu : 0x80000000u);
}
__device__ __forceinline__ float unfkey(unsigned u) {
    unsigned b = u ^ ((u & 0x80000000u) ? 0x80000000u : 0xFFFFFFFFu);
    return __uint_as_float(b);
}

__device__ __forceinline__ unsigned tf32_hi_bits(float x) {
    return __float_as_uint(x) & 0xFFFFE000u;
}

__device__ __forceinline__ void mma_tf32(float& d0, float& d1, float& d2, float& d3,
                                         unsigned a0, unsigned a1, unsigned a2, unsigned a3,
                                         unsigned b0, unsigned b1) {
    asm volatile(
        "mma.sync.aligned.m16n8k8.row.col.f32.tf32.tf32.f32 "
        "{%0,%1,%2,%3}, {%4,%5,%6,%7}, {%8,%9}, {%0,%1,%2,%3};"
        : "+f"(d0), "+f"(d1), "+f"(d2), "+f"(d3)
        : "r"(a0), "r"(a1), "r"(a2), "r"(a3), "r"(b0), "r"(b1));
}

__device__ __forceinline__ float block_max(float v, float* sred) {
    #pragma unroll
    for (int o = 16; o; o >>= 1) v = fmaxf(v, __shfl_xor_sync(0xFFFFFFFFu, v, o));
    if ((threadIdx.x & 31) == 0) sred[threadIdx.x >> 5] = v;
    __syncthreads();
    if (threadIdx.x < 32) {
        float x = (threadIdx.x < NW) ? sred[threadIdx.x] : -CUDART_INF_F;
        #pragma unroll
        for (int o = 8; o; o >>= 1) x = fmaxf(x, __shfl_xor_sync(0xFFFFFFFFu, x, o));
        if (threadIdx.x == 0) sred[0] = x;
    }
    __syncthreads();
    v = sred[0];
    __syncthreads();
    return v;
}

__device__ __forceinline__ float block_sum(float v, float* sred) {
    #pragma unroll
    for (int o = 16; o; o >>= 1) v += __shfl_xor_sync(0xFFFFFFFFu, v, o);
    if ((threadIdx.x & 31) == 0) sred[threadIdx.x >> 5] = v;
    __syncthreads();
    if (threadIdx.x < 32) {
        float x = (threadIdx.x < NW) ? sred[threadIdx.x] : 0.0f;
        #pragma unroll
        for (int o = 8; o; o >>= 1) x += __shfl_xor_sync(0xFFFFFFFFu, x, o);
        if (threadIdx.x == 0) sred[0] = x;
    }
    __syncthreads();
    v = sred[0];
    __syncthreads();
    return v;
}

__global__ void swizzle_k_kernel(const float* __restrict__ k) {
    int t = blockIdx.x * blockDim.x + threadIdx.x;
    int lane = t & 31;
    int st   = (t >> 5) & 15;
    int blk  = (t >> 9) & (NBLK_MAX - 1);
    int h    = t >> 17;
    int g  = lane >> 2;
    int tg = lane & 3;
    int key = blk * 16 + g;
    int d   = st * 8 + tg;
    const float* kb = k + ((size_t)(h * T_SRC + key)) * HID + d;
    g_kfrag[t] = make_float4(kb[0], kb[8 * HID], kb[4], kb[8 * HID + 4]);
}

__global__ void swizzle_v_kernel(const float* __restrict__ v) {
    int t = blockIdx.x * blockDim.x + threadIdx.x;
    int lane = t & 31;
    int jb   = (t >> 5) & (NJBLK - 1);
    int dt   = (t >> 14) & (NDTILE - 1);
    int h    = t >> 17;
    int g  = lane >> 2;
    int tg = lane & 3;
    int d  = dt * 16 + g;
    int j  = jb * 8 + tg;
    const float* vb = v + (size_t)(h * T_SRC) * HID;
    g_vfrag[t] = make_float4(vb[(size_t)j * HID + d],
                             vb[(size_t)j * HID + d + 8],
                             vb[(size_t)(j + 4) * HID + d],
                             vb[(size_t)(j + 4) * HID + d + 8]);
}

__global__ __launch_bounds__(NT, 1)
void tree_attn_r17(const float* __restrict__ q,
                   const float* __restrict__ v,
                   float* __restrict__ out) {
    extern __shared__ char smem_raw[];
    float*    s_sc   = (float*)smem_raw;                     // [QT][T_SRC] (float | fkey)
    unsigned* s_su   = (unsigned*)smem_raw;                  // key view (sparse)
    float*    s_q    = s_sc + W_SC;
    int*      s_idx  = (int*)(s_q + W_Q);
    float*    s_w    = (float*)(s_idx + W_IDX);
    unsigned* s_h3   = (unsigned*)(s_w + W_W);
    int*      s_cand = (int*)(s_h3 + W_H3);
    int*      s_c2   = (int*)(s_cand + W_CAND);
    int*      s_eq   = (int*)(s_c2 + W_C2);
    unsigned* s_ctrl = (unsigned*)(s_eq + W_EQ);
    float*    s_av   = (float*)s_h3;                         // [2][8][128] (AV partials)
    unsigned* s_b3   = s_ctrl;
    unsigned* s_ngt3 = s_ctrl + 8;
    unsigned* s_gtc  = s_ctrl + 16;
    unsigned* s_cc   = s_ctrl + 24;
    unsigned* s_ovf  = s_ctrl + 32;
    unsigned* s_misc = s_ctrl + 40;
    float*    s_inv  = (float*)(s_ctrl + 48);
    __shared__ float s_redf[NW];

    const int tile = (NTILES - 1) - blockIdx.x;
    const int h    = blockIdx.y;
    const int tid  = threadIdx.x;
    const int wid  = tid >> 5;
    const int lane = tid & 31;
    const unsigned lmlt = (1u << lane) - 1u;
    const int qi0  = tile * QT;
    const int n_max = qi0 + QT;
    const bool sparse = (qi0 >= TDENSE);

    const float* vbase = v + (size_t)h * T_SRC * HID;

    for (int d = tid; d < QT * HID; d += NT)
        s_q[d] = q[((size_t)h * T_DST + qi0) * HID + d];
    if (sparse) {
        for (int i = tid; i < QT * HPAD; i += NT) s_h3[i] = 0u;
        if (tid < 8) { s_gtc[tid] = 0u; s_cc[tid] = 0u; s_ovf[tid] = 0u; }
    }
    __syncthreads();

    const int g  = lane >> 2;
    const int tg = lane & 3;
    unsigned bh[16][2], bl[16][2];
    #pragma unroll
    for (int st = 0; st < 16; st++) {
        float x0 = s_q[g * HID + st * 8 + tg];
        float x1 = s_q[g * HID + st * 8 + tg + 4];
        unsigned h0 = tf32_hi_bits(x0);
        unsigned h1 = tf32_hi_bits(x1);
        bh[st][0] = h0;
        bh[st][1] = h1;
        bl[st][0] = __float_as_uint(x0 - __uint_as_float(h0));
        bl[st][1] = __float_as_uint(x1 - __uint_as_float(h1));
    }

    // ---- scores via 3xTF32 mma with 3 INDEPENDENT accumulator chains ----
    float mx[QT];
    #pragma unroll
    for (int s = 0; s < QT; s++) mx[s] = -CUDART_INF_F;

    const int nblk = (n_max + 15) >> 4;
    for (int blk = wid; blk < nblk; blk += NW) {
        float d0 = 0.f, d1 = 0.f, d2 = 0.f, d3 = 0.f;   // hi*hi chain
        float e0 = 0.f, e1 = 0.f, e2 = 0.f, e3 = 0.f;   // hi*lo chain
        float f0 = 0.f, f1 = 0.f, f2 = 0.f, f3 = 0.f;   // lo*hi chain
        const float4* fk = g_kfrag + ((size_t)(h * NBLK_MAX + blk) * 16) * 32 + lane;
        #pragma unroll
        for (int st = 0; st < 16; st++) {
            float4 a4 = fk[st * 32];
            unsigned a0 = tf32_hi_bits(a4.x), a1 = tf32_hi_bits(a4.y);
            unsigned a2 = tf32_hi_bits(a4.z), a3 = tf32_hi_bits(a4.w);
            unsigned l0 = __float_as_uint(a4.x - __uint_as_float(a0));
            unsigned l1 = __float_as_uint(a4.y - __uint_as_float(a1));
            unsigned l2 = __float_as_uint(a4.z - __uint_as_float(a2));
            unsigned l3 = __float_as_uint(a4.w - __uint_as_float(a3));
            mma_tf32(d0, d1, d2, d3, a0, a1, a2, a3, bh[st][0], bh[st][1]);
            mma_tf32(e0, e1, e2, e3, a0, a1, a2, a3, bl[st][0], bl[st][1]);
            mma_tf32(f0, f1, f2, f3, l0, l1, l2, l3, bh[st][0], bh[st][1]);
        }
        d0 = (d0 + e0) + f0;
        d1 = (d1 + e1) + f1;
        d2 = (d2 + e2) + f2;
        d3 = (d3 + e3) + f3;
        const int kA = blk * 16 + g;
        const int kB = kA + 8;
        const int q0 = tg * 2;
        const int q1 = q0 + 1;
        float v0 = (kA <= qi0 + q0) ? d0 : -CUDART_INF_F;
        float v1 = (kA <= qi0 + q1) ? d1 : -CUDART_INF_F;
        float v2 = (kB <= qi0 + q0) ? d2 : -CUDART_INF_F;
        float v3 = (kB <= qi0 + q1) ? d3 : -CUDART_INF_F;
        mx[q0] = fmaxf(mx[q0], fmaxf(v0, v2));
        mx[q1] = fmaxf(mx[q1], fmaxf(v1, v3));
        if (sparse) {
            unsigned k0 = fkey(v0), k1 = fkey(v1), k2 = fkey(v2), k3 = fkey(v3);
            s_su[q0 * T_SRC + kA] = k0;
            s_su[q1 * T_SRC + kA] = k1;
            s_su[q0 * T_SRC + kB] = k2;
            s_su[q1 * T_SRC + kB] = k3;
            atomicAdd(&s_h3[q0 * HPAD + (k0 >> 24)], 1u);
            atomicAdd(&s_h3[q1 * HPAD + (k1 >> 24)], 1u);
            atomicAdd(&s_h3[q0 * HPAD + (k2 >> 24)], 1u);
            atomicAdd(&s_h3[q1 * HPAD + (k3 >> 24)], 1u);
        } else {
            s_sc[q0 * T_SRC + kA] = v0;
            s_sc[q1 * T_SRC + kA] = v1;
            s_sc[q0 * T_SRC + kB] = v2;
            s_sc[q1 * T_SRC + kB] = v3;
        }
    }
    __syncthreads();

    float m[QT];
    #pragma unroll
    for (int s = 0; s < QT; s++) m[s] = block_max(mx[s], s_redf);

    if (!sparse) {
        // ================= dense causal softmax =================
        float psum[QT];
        #pragma unroll
        for (int s = 0; s < QT; s++) psum[s] = 0.0f;
        for (int j = tid; j < n_max; j += NT) {
            #pragma unroll
            for (int s = 0; s < QT; s++) {
                float sc = s_sc[s * T_SRC + j];
                float e = (j <= qi0 + s) ? __expf(sc - m[s]) : 0.0f;
                s_sc[s * T_SRC + j] = e;
                psum[s] += e;
            }
        }
        #pragma unroll
        for (int s = 0; s < QT; s++) {
            float iv = 1.0f / block_sum(psum[s], s_redf);
            if (tid == 0) s_inv[s] = iv;
        }

        // ---- dense AV via 3xTF32 mma, 3 independent chains ----
        {
            const int dt = wid & 7;
            const int jh = wid >> 3;
            const int jchunks = n_max >> 3;
            float e0 = 0.f, e1 = 0.f, e2 = 0.f, e3 = 0.f;
            float u0 = 0.f, u1 = 0.f, u2 = 0.f, u3 = 0.f;
            float w0 = 0.f, w1 = 0.f, w2 = 0.f, w3 = 0.f;
            const float4* fv = g_vfrag + ((size_t)((h * NDTILE + dt) * NJBLK)) * 32 + lane;
            for (int c = jh; c < jchunks; c += 2) {
                float4 a4 = fv[c * 32];
                unsigned a0 = tf32_hi_bits(a4.x), a1 = tf32_hi_bits(a4.y);
                unsigned a2 = tf32_hi_bits(a4.z), a3 = tf32_hi_bits(a4.w);
                unsigned l0 = __float_as_uint(a4.x - __uint_as_float(a0));
                unsigned l1 = __float_as_uint(a4.y - __uint_as_float(a1));
                unsigned l2 = __float_as_uint(a4.z - __uint_as_float(a2));
                unsigned l3 = __float_as_uint(a4.w - __uint_as_float(a3));
                float p0 = s_sc[g * T_SRC + c * 8 + tg];
                float p1 = s_sc[g * T_SRC + c * 8 + tg + 4];
                unsigned ph0 = tf32_hi_bits(p0);
                unsigned ph1 = tf32_hi_bits(p1);
                unsigned pl0 = __float_as_uint(p0 - __uint_as_float(ph0));
                unsigned pl1 = __float_as_uint(p1 - __uint_as_float(ph1));
                mma_tf32(e0, e1, e2, e3, a0, a1, a2, a3, ph0, ph1);
                mma_tf32(u0, u1, u2, u3, l0, l1, l2, l3, ph0, ph1);
                mma_tf32(w0, w1, w2, w3, a0, a1, a2, a3, pl0, pl1);
            }
            e0 = (e0 + u0) + w0;
            e1 = (e1 + u1) + w1;
            e2 = (e2 + u2) + w2;
            e3 = (e3 + u3) + w3;
            int base = jh * 1024 + (tg * 2) * HID + dt * 16 + g;
            s_av[base]           = e0;
            s_av[base + HID]     = e1;
            s_av[base + 8]       = e2;
            s_av[base + HID + 8] = e3;
        }
        __syncthreads();
        #pragma unroll
        for (int i = tid; i < QT * HID; i += NT) {
            int qq = i >> 7;
            out[((size_t)h * T_DST + qi0 + qq) * HID + (i & (HID - 1))] =
                (s_av[i] + s_av[1024 + i]) * s_inv[qq];
        }
    } else {
        // ================= sparse: exact top-128 (keys in s_su) =================

        // ---- per-warp bin scan ----
        if (wid < QT) {
            const int s = wid;
            unsigned gg = 0;
            #pragma unroll
            for (int b = 0; b < 8; b++) gg += s_h3[s * HPAD + lane * 8 + b];
            unsigned run = gg;
            #pragma unroll
            for (int o = 1; o < 32; o <<= 1) {
                unsigned u = __shfl_down_sync(0xFFFFFFFFu, run, o);
                if (lane + o < 32) run += u;
            }
            unsigned S = run - gg;
            int found = (run >= KTOP && S < KTOP);
            unsigned blb = 0, acc2 = 0;
            if (found) {
                acc2 = S;
                #pragma unroll 1
                for (int b = 7; b >= 0; b--) {
                    unsigned c = s_h3[s * HPAD + lane * 8 + b];
                    if (acc2 + c >= KTOP) { blb = lane * 8 + b; break; }
                    acc2 += c;
                }
            }
            unsigned fmask = __ballot_sync(0xFFFFFFFFu, found);
            int flane = __ffs(fmask) - 1;
            blb  = __shfl_sync(0xFFFFFFFFu, blb, flane);
            acc2 = __shfl_sync(0xFFFFFFFFu, acc2, flane);
            if (lane == 0) { s_b3[s] = blb; s_ngt3[s] = acc2; }
        }
        __syncthreads();

        // ---- compact sweep: plain predicated atomics ----
        {
            unsigned b3v[QT];
            #pragma unroll
            for (int s = 0; s < QT; s++) b3v[s] = s_b3[s];
            for (int j = tid; j < n_max; j += NT) {
                #pragma unroll
                for (int s = 0; s < QT; s++) {
                    unsigned bin = s_su[s * T_SRC + j] >> 24;
                    if (bin >= b3v[s]) {
                        if (bin > b3v[s]) {
                            unsigned p = atomicAdd(&s_gtc[s], 1u);
                            s_idx[s * KTOP + p] = j;
                        } else {
                            unsigned p = atomicAdd(&s_cc[s], 1u);
                            if (p < CAND_CAP) s_cand[s * CAND_CAP + p] = j;
                        }
                    }
                }
            }
        }
        __syncthreads();

        // ---- per-warp refinement ----
        if (wid < QT) {
            const int s = wid;
            const unsigned* sc = s_su + s * T_SRC;
            int nc = (int)s_cc[s];
            unsigned ngt = s_ngt3[s];
            bool ok = (nc <= CAND_CAP);
            int cur = 0;
            int* lists[2] = { s_cand + s * CAND_CAP, s_c2 + s * C2_CAP };
            const int caps[2] = { CAND_CAP, C2_CAP };

            #pragma unroll 1
            for (int lvl = 2; lvl >= 0 && ok; lvl--) {
                const int shift = lvl * 8;
                for (int b = lane; b < 257; b += 32) s_h3[s * HPAD + b] = 0u;
                __syncwarp();
                const int rb = (nc + 31) & ~31;
                for (int i = lane; i < rb; i += 32) {
                    unsigned bin = 256u;
                    if (i < nc) bin = (sc[lists[cur][i]] >> shift) & 255u;
                    unsigned peers = __match_any_sync(0xFFFFFFFFu, bin);
                    if ((__ffs(peers) - 1) == lane)
                        s_h3[s * HPAD + bin] += (unsigned)__popc(peers);
                }
                __syncwarp();
                unsigned gg = 0;
                #pragma unroll
                for (int b = 0; b < 8; b++) gg += s_h3[s * HPAD + lane * 8 + b];
                unsigned run = gg;
                #pragma unroll
                for (int o = 1; o < 32; o <<= 1) {
                    unsigned u = __shfl_down_sync(0xFFFFFFFFu, run, o);
                    if (lane + o < 32) run += u;
                }
                unsigned S = run - gg;
                int found = (ngt + run >= KTOP && ngt + S < KTOP);
                unsigned blb = 0;
                if (found) {
                    unsigned acc2 = ngt + S;
                    #pragma unroll 1
                    for (int b = 7; b >= 0; b--) {
                        unsigned c = s_h3[s * HPAD + lane * 8 + b];
                        if (acc2 + c >= KTOP) { blb = lane * 8 + b; break; }
                        acc2 += c;
                    }
                }
                unsigned fmask = __ballot_sync(0xFFFFFFFFu, found);
                int flane = __ffs(fmask) - 1;
                blb = __shfl_sync(0xFFFFFFFFu, blb, flane);
                const int dst = cur ^ 1;
                int* dl = lists[dst];
                const int dcap = caps[dst];
                unsigned wg = ngt, we = 0;
                for (int i = lane; i < rb; i += 32) {
                    unsigned bin = 256u; int j = 0;
                    if (i < nc) { j = lists[cur][i]; bin = (sc[j] >> shift) & 255u; }
                    bool gt = (bin > blb) && (bin <= 255u);
                    bool eq = (bin == blb);
                    unsigned mg = __ballot_sync(0xFFFFFFFFu, gt);
                    unsigned me = __ballot_sync(0xFFFFFFFFu, eq);
                    if (gt) s_idx[s * KTOP + wg + __popc(mg & lmlt)] = j;
                    if (eq) {
                        unsigned p = we + __popc(me & lmlt);
                        if ((int)p < dcap) dl[p] = j;
                    }
                    wg += __popc(mg); we += __popc(me);
                }
                ngt = wg;
                nc = (int)we;
                cur = dst;
                if (nc > dcap) ok = false;
                __syncwarp();
            }
            if (ok) {
                const int need = KTOP - (int)ngt;
                const int* tl = lists[cur];
                for (int i = lane; i < nc; i += 32) {
                    int ji = tl[i];
                    int rank = 0;
                    for (int m2 = 0; m2 < nc; m2++) rank += (tl[m2] < ji);
                    if (rank < need) s_idx[s * KTOP + (int)ngt + rank] = ji;
                }
            } else if (lane == 0) {
                s_ovf[s] = 1u;
            }
        }
        __syncthreads();

        // ---- rare fallback: full 4-level radix on keys ----
        unsigned ovf_any = 0;
        #pragma unroll
        for (int s = 0; s < QT; s++) ovf_any |= s_ovf[s];
        if (ovf_any) {
            const int bound = ((n_max + NT - 1) / NT) * NT;
            #pragma unroll 1
            for (int s = 0; s < QT; s++) {
                if (!s_ovf[s]) continue;
                const unsigned* sc = s_su + s * T_SRC;
                unsigned prefix = 0, ngt = 0;
                #pragma unroll 1
                for (int level = 3; level >= 0; level--) {
                    for (int b = tid; b < 257; b += NT) s_h3[b] = 0u;
                    __syncthreads();
                    const unsigned shift = level * 8;
                    const unsigned pmask = (level == 3) ? 0u : (0xFFFFFFFFu << (shift + 8));
                    for (int j = tid; j < bound; j += NT) {
                        unsigned bin = 256u;
                        if (j < n_max) {
                            unsigned key = sc[j];
                            if ((key & pmask) == prefix) bin = (key >> shift) & 0xFFu;
                        }
                        unsigned peers = __match_any_sync(0xFFFFFFFFu, bin);
                        if ((__ffs(peers) - 1) == lane)
                            atomicAdd(&s_h3[bin], (unsigned)__popc(peers));
                    }
                    __syncthreads();
                    if (tid < 32) {
                        unsigned gg = 0;
                        #pragma unroll
                        for (int b = 0; b < 8; b++) gg += s_h3[tid * 8 + b];
                        unsigned run = gg;
                        #pragma unroll
                        for (int o = 1; o < 32; o <<= 1) {
                            unsigned u = __shfl_down_sync(0xFFFFFFFFu, run, o);
                            if (tid + o < 32) run += u;
                        }
                        unsigned S = run - gg;
                        if (ngt + run >= KTOP && ngt + S < KTOP) {
                            unsigned acc2 = ngt + S;
                            #pragma unroll 1
                            for (int b = 7; b >= 0; b--) {
                                unsigned c = s_h3[tid * 8 + b];
                                if (acc2 + c >= KTOP) {
                                    s_misc[0] = prefix | ((unsigned)(tid * 8 + b) << shift);
                                    s_misc[1] = acc2;
                                    break;
                                }
                                acc2 += c;
                            }
                        }
                    }
                    __syncthreads();
                    prefix = s_misc[0];
                    ngt = s_misc[1];
                    __syncthreads();
                }
                const unsigned t_key = prefix;
                if (tid == 0) { s_misc[2] = 0u; s_misc[3] = 0u; }
                __syncthreads();
                for (int j = tid; j < n_max; j += NT) {
                    unsigned key = sc[j];
                    if (key > t_key) {
                        unsigned p = atomicAdd(&s_misc[2], 1u);
                        s_idx[s * KTOP + p] = j;
                    } else if (key == t_key) {
                        unsigned p = atomicAdd(&s_misc[3], 1u);
                        if (p < KTOP) s_eq[p] = j;
                    }
                }
                __syncthreads();
                const int neq = (int)s_misc[3];
                const int need = KTOP - (int)ngt;
                if (need < neq && tid == 0) {
                    int c = (neq < KTOP) ? neq : KTOP;
                    for (int a = 0; a < need; a++) {
                        int mb = a;
                        for (int b = a + 1; b < c; b++)
                            if (s_eq[b] < s_eq[mb]) mb = b;
                        int t2 = s_eq[a]; s_eq[a] = s_eq[mb]; s_eq[mb] = t2;
                    }
                }
                __syncthreads();
                for (int a = tid; a < need; a += NT) s_idx[s * KTOP + (int)ngt + a] = s_eq[a];
                __syncthreads();
            }
        }

        // ---- per-warp softmax weights ----
        if (wid < QT) {
            const int s = wid;
            float psum = 0.0f;
            #pragma unroll
            for (int i = 0; i < KTOP / 32; i++) {
                int a = lane + i * 32;
                float sc = unfkey(s_su[s * T_SRC + s_idx[s * KTOP + a]]);
                float e = __expf(sc - m[s]);
                s_w[s * KTOP + a] = e;
                psum += e;
            }
            #pragma unroll
            for (int o = 16; o; o >>= 1) psum += __shfl_xor_sync(0xFFFFFFFFu, psum, o);
            if (lane == 0) s_inv[s] = 1.0f / psum;
        }
        __syncthreads();

        // ---- sparse AV: warp per (query, row-half), float4 lanes ----
        {
            const int s  = wid & 7;
            const int jh = wid >> 3;
            const int* isrc = s_idx + s * KTOP;
            const float* wsrc = s_w + s * KTOP;
            float4 acc4 = make_float4(0.f, 0.f, 0.f, 0.f);
            const int a0 = jh * 64;
            #pragma unroll 2
            for (int a = a0; a < a0 + 64; a += 2) {
                int j0 = isrc[a];
                int j1 = isrc[a + 1];
                float w0 = wsrc[a];
                float w1 = wsrc[a + 1];
                float4 v0 = *(const float4*)(vbase + (size_t)j0 * HID + lane * 4);
                float4 v1 = *(const float4*)(vbase + (size_t)j1 * HID + lane * 4);
                acc4.x = fmaf(w0, v0.x, acc4.x);
                acc4.y = fmaf(w0, v0.y, acc4.y);
                acc4.z = fmaf(w0, v0.z, acc4.z);
                acc4.w = fmaf(w0, v0.w, acc4.w);
                acc4.x = fmaf(w1, v1.x, acc4.x);
                acc4.y = fmaf(w1, v1.y, acc4.y);
                acc4.z = fmaf(w1, v1.z, acc4.z);
                acc4.w = fmaf(w1, v1.w, acc4.w);
            }
            ((float4*)(s_av + jh * 1024 + s * HID))[lane] = acc4;
        }
        __syncthreads();
        #pragma unroll
        for (int i = tid; i < QT * HID; i += NT) {
            int qq = i >> 7;
            out[((size_t)h * T_DST + qi0 + qq) * HID + (i & (HID - 1))] =
                (s_av[i] + s_av[1024 + i]) * s_inv[qq];
        }
    }
}

extern "C" void kernel_launch(void* const* d_in, const int* in_sizes, int n_in,
                              void* d_out, int out_size) {
    const float* q = (const float*)d_in[0];
    const float* k = (const float*)d_in[1];
    const float* v = (const float*)d_in[2];
    float* out = (float*)d_out;

    swizzle_k_kernel<<<KFRAG_N / 256, 256>>>(k);
    swizzle_v_kernel<<<VFRAG_N / 256, 256>>>(v);

    cudaFuncSetAttribute(tree_attn_r17,
                         cudaFuncAttributeMaxDynamicSharedMemorySize, DYN_BYTES);

    dim3 grid(NTILES, NHEADS);
    tree_attn_r17<<<grid, NT, DYN_BYTES>>>(q, v, out);
}